// round 4
// baseline (speedup 1.0000x reference)
#include <cuda_runtime.h>
#include <cstdint>
#include <math.h>

#define B      512
#define S      200
#define H      1024
#define V      100
#define EMB    512
#define INSZ   1024
#define H3     3072
#define START_TOK 1
#define NTH    128

#define SA_STRIDE 136   // floats; 16B-aligned rows, bank-shift 8
#define SW_STRIDE 68    // floats; 16B-aligned rows, bank-shift 4

// ---------------- persistent scratch ----------------
__device__ float g_decode[B * INSZ];
__device__ float g_h0[B * H];
__device__ float g_h1[B * H];
__device__ float g_h2[B * H];
__device__ float g_gi0[B * H3];
__device__ float g_gi1[B * H3];
__device__ float g_gh0[B * H3];
__device__ float g_gh1[B * H3];
__device__ float g_gh2[B * H3];
__device__ float g_gh3[B * H3];
__device__ float g_gi0c[B * H3];
__device__ float g_tokt[V * H3];
__device__ float g_logc[B * V];
__device__ unsigned g_bar_count;
__device__ unsigned g_bar_phase;

// ---------------- grid barrier ----------------
__device__ __forceinline__ void grid_bar()
{
    __syncthreads();
    if (threadIdx.x == 0) {
        __threadfence();
        volatile unsigned* php = &g_bar_phase;
        unsigned ph = *php;
        if (atomicAdd(&g_bar_count, 1u) == gridDim.x - 1u) {
            g_bar_count = 0u;
            __threadfence();
            atomicAdd(&g_bar_phase, 1u);
        } else {
            while (*php == ph) { __nanosleep(32); }
        }
        __threadfence();
    }
    __syncthreads();
}

// ---------------- f32x2 helpers ----------------
__device__ __forceinline__ unsigned long long pack2(float x)
{
    unsigned long long r;
    asm("mov.b64 %0, {%1, %1};" : "=l"(r) : "f"(x));
    return r;
}
__device__ __forceinline__ void fma2(unsigned long long& d, unsigned long long a,
                                     unsigned long long b)
{
    asm("fma.rn.f32x2 %0, %1, %2, %0;" : "+l"(d) : "l"(a), "l"(b));
}
__device__ __forceinline__ void unpack2(unsigned long long v, float& lo, float& hi)
{
    asm("mov.b64 {%0, %1}, %2;" : "=f"(lo), "=f"(hi) : "l"(v));
}
__device__ __forceinline__ void lds_v2u64(unsigned long long& x, unsigned long long& y,
                                          uint32_t a)
{
    asm volatile("ld.shared.v2.u64 {%0, %1}, [%2];" : "=l"(x), "=l"(y) : "r"(a));
}
__device__ __forceinline__ void sts_f32(uint32_t a, float v)
{
    asm volatile("st.shared.f32 [%0], %1;" :: "r"(a), "f"(v));
}

// ---------------- GEMM tile job ----------------
struct Job {
    const float* A; const float* W; const float* bias; const float* Cadd; float* C;
    int lda, ldw, ldadd, ldc, Mlim, Nlim, m0, n0, kbeg, klen;
};

__device__ __forceinline__ Job mkjob(
    const float* A, int lda, const float* W, int ldw,
    const float* bias, const float* Cadd, int ldadd,
    float* C, int ldc, int Mlim, int Nlim, int m0, int n0, int kbeg, int klen)
{
    Job j;
    j.A = A; j.W = W; j.bias = bias; j.Cadd = Cadd; j.C = C;
    j.lda = lda; j.ldw = ldw; j.ldadd = ldadd; j.ldc = ldc;
    j.Mlim = Mlim; j.Nlim = Nlim; j.m0 = m0; j.n0 = n0; j.kbeg = kbeg; j.klen = klen;
    return j;
}

// 128x64 tile, 128 threads, 8x8 per thread via f32x2, double-buffered
__device__ __noinline__ void gemm_tile(const Job jb, uint32_t sAb, uint32_t sWb)
{
    const int tid = threadIdx.x;
    const int ty = tid >> 3;        // 0..15 -> rows ty*8..+7
    const int tx = tid & 7;         // 0..7  -> cols tx*4 (+32 group)
    const int lrow = tid >> 2;      // 0..31 loader row
    const int lkq  = tid & 3;       // 0..3  loader k-quad

    // global loader pointers
    const float* aP[4]; bool aV[4];
#pragma unroll
    for (int f = 0; f < 4; f++) {
        int m = jb.m0 + f * 32 + lrow;
        aV[f] = (m < jb.Mlim);
        aP[f] = jb.A + (size_t)(aV[f] ? m : 0) * jb.lda + jb.kbeg + lkq * 4;
    }
    const float* wP[2]; bool wV[2];
#pragma unroll
    for (int f = 0; f < 2; f++) {
        int n = jb.n0 + f * 32 + lrow;
        wV[f] = (n < jb.Nlim);
        wP[f] = jb.W + (size_t)(wV[f] ? n : 0) * jb.ldw + jb.kbeg + lkq * 4;
    }

    // STS swizzled row bases (swizzle key = k>>2 = lkq)
    uint32_t stA[4], stW[2];
#pragma unroll
    for (int f = 0; f < 4; f++)
        stA[f] = sAb + (uint32_t)(((lkq * 4) * SA_STRIDE + (((f * 32) + lrow) ^ (lkq << 3))) << 2);
#pragma unroll
    for (int f = 0; f < 2; f++)
        stW[f] = sWb + (uint32_t)(((lkq * 4) * SW_STRIDE + (((f * 32) + lrow) ^ (lkq << 3))) << 2);

    const uint32_t bufA = (uint32_t)(16 * SA_STRIDE * 4);
    const uint32_t bufW = (uint32_t)(16 * SW_STRIDE * 4);

    unsigned long long acc[8][4];
#pragma unroll
    for (int i = 0; i < 8; i++)
#pragma unroll
        for (int j = 0; j < 4; j++) acc[i][j] = 0ull;

    float4 aR[4], wR[2];
    const float4 zero4 = make_float4(0.f, 0.f, 0.f, 0.f);

#define LOADG() do { \
    _Pragma("unroll") for (int f = 0; f < 4; f++) { \
        aR[f] = aV[f] ? *reinterpret_cast<const float4*>(aP[f]) : zero4; aP[f] += 16; } \
    _Pragma("unroll") for (int f = 0; f < 2; f++) { \
        wR[f] = wV[f] ? *reinterpret_cast<const float4*>(wP[f]) : zero4; wP[f] += 16; } \
} while (0)

#define STS(bsel) do { \
    uint32_t offa = (bsel) ? bufA : 0u; \
    uint32_t offw = (bsel) ? bufW : 0u; \
    _Pragma("unroll") for (int f = 0; f < 4; f++) { \
        uint32_t a0 = stA[f] + offa; \
        sts_f32(a0, aR[f].x); \
        sts_f32(a0 + SA_STRIDE * 4, aR[f].y); \
        sts_f32(a0 + SA_STRIDE * 8, aR[f].z); \
        sts_f32(a0 + SA_STRIDE * 12, aR[f].w); } \
    _Pragma("unroll") for (int f = 0; f < 2; f++) { \
        uint32_t a0 = stW[f] + offw; \
        sts_f32(a0, wR[f].x); \
        sts_f32(a0 + SW_STRIDE * 4, wR[f].y); \
        sts_f32(a0 + SW_STRIDE * 8, wR[f].z); \
        sts_f32(a0 + SW_STRIDE * 12, wR[f].w); } \
} while (0)

#define COMPUTE(bsel) do { \
    uint32_t baA = sAb + ((bsel) ? bufA : 0u); \
    uint32_t baW = sWb + ((bsel) ? bufW : 0u); \
    _Pragma("unroll") for (int kk = 0; kk < 16; kk++) { \
        uint32_t sw = (uint32_t)((kk >> 2) << 3); \
        uint32_t aad = baA + (uint32_t)((kk * SA_STRIDE + ((ty * 8) ^ sw)) << 2); \
        float4 av0, av1; \
        asm volatile("ld.shared.v4.f32 {%0,%1,%2,%3}, [%4];" \
            : "=f"(av0.x), "=f"(av0.y), "=f"(av0.z), "=f"(av0.w) : "r"(aad)); \
        asm volatile("ld.shared.v4.f32 {%0,%1,%2,%3}, [%4];" \
            : "=f"(av1.x), "=f"(av1.y), "=f"(av1.z), "=f"(av1.w) : "r"(aad + 16)); \
        unsigned long long w0, w1, w2, w3; \
        uint32_t wad0 = baW + (uint32_t)((kk * SW_STRIDE + ((tx * 4) ^ sw)) << 2); \
        uint32_t wad1 = baW + (uint32_t)((kk * SW_STRIDE + (((tx * 4) + 32) ^ sw)) << 2); \
        lds_v2u64(w0, w1, wad0); \
        lds_v2u64(w2, w3, wad1); \
        float as[8] = {av0.x, av0.y, av0.z, av0.w, av1.x, av1.y, av1.z, av1.w}; \
        _Pragma("unroll") for (int i = 0; i < 8; i++) { \
            unsigned long long ap = pack2(as[i]); \
            fma2(acc[i][0], ap, w0); \
            fma2(acc[i][1], ap, w1); \
            fma2(acc[i][2], ap, w2); \
            fma2(acc[i][3], ap, w3); } \
    } \
} while (0)

    const int nch = jb.klen >> 4;
    LOADG();
    STS(0);
    __syncthreads();
    int cur = 0;
    for (int c = 0; c < nch; c++) {
        if (c + 1 < nch) LOADG();
        COMPUTE(cur);
        if (c + 1 < nch) {
            STS(cur ^ 1);
            __syncthreads();
            cur ^= 1;
        }
    }
    __syncthreads();   // protect smem for next unit

#undef LOADG
#undef STS
#undef COMPUTE

    // epilogue
#pragma unroll
    for (int i = 0; i < 8; i++) {
        int m = jb.m0 + ty * 8 + i;
        if (m >= jb.Mlim) continue;
        float* cr = jb.C + (size_t)m * jb.ldc;
        const float* ca = jb.Cadd ? (jb.Cadd + (size_t)m * jb.ldadd) : nullptr;
#pragma unroll
        for (int g = 0; g < 2; g++) {
#pragma unroll
            for (int p = 0; p < 2; p++) {
                float lo, hi;
                unpack2(acc[i][g * 2 + p], lo, hi);
                int n = jb.n0 + g * 32 + tx * 4 + p * 2;
                if (n < jb.Nlim) {
                    float v = lo;
                    if (jb.bias) v += jb.bias[n];
                    if (ca) v += ca[n];
                    cr[n] = v;
                }
                if (n + 1 < jb.Nlim) {
                    float v = hi;
                    if (jb.bias) v += jb.bias[n + 1];
                    if (ca) v += ca[n + 1];
                    cr[n + 1] = v;
                }
            }
        }
    }
}

__device__ __forceinline__ float sigm(float x)
{
    return 1.0f / (1.0f + __expf(-x));
}

// ---------------- persistent kernel ----------------
__global__ __launch_bounds__(NTH, 4) void decoder_k(
    const int* __restrict__ inputs, const float* __restrict__ z,
    const float* __restrict__ cond, const float* __restrict__ emb,
    const float* __restrict__ i2h_w, const float* __restrict__ i2h_b,
    const float* __restrict__ out_w, const float* __restrict__ out_b,
    const float* __restrict__ wih0, const float* __restrict__ whh0,
    const float* __restrict__ bih0, const float* __restrict__ bhh0,
    const float* __restrict__ wih1, const float* __restrict__ whh1,
    const float* __restrict__ bih1, const float* __restrict__ bhh1,
    const float* __restrict__ wih2, const float* __restrict__ whh2,
    const float* __restrict__ bih2, const float* __restrict__ bhh2,
    float* __restrict__ out)
{
    __shared__ __align__(16) float shA[2 * 16 * SA_STRIDE];
    __shared__ __align__(16) float shW[2 * 16 * SW_STRIDE];
    const uint32_t sAb = (uint32_t)__cvta_generic_to_shared(&shA[0]);
    const uint32_t sWb = (uint32_t)__cvta_generic_to_shared(&shW[0]);

    const int tid = threadIdx.x;
    const unsigned nb = gridDim.x;
    const int gstride = nb * NTH;

    // ---- P1: decode = concat(z, cond) ----
    for (int idx = blockIdx.x * NTH + tid; idx < B * INSZ; idx += gstride) {
        int b = idx >> 10, jx = idx & 1023;
        g_decode[idx] = (jx < 512) ? z[b * 512 + jx] : cond[b * 512 + jx - 512];
    }
    grid_bar();

    // ---- P2: precomputes ----
    {
        // h_init 64 | gi0c 192 | tokt 48 | logc 8  => 312 units
        for (int u = blockIdx.x; u < 312; u += nb) {
            Job jb;
            if (u < 64) {
                int mt = u >> 4, nt = u & 15;
                jb = mkjob(g_decode, INSZ, i2h_w, INSZ, i2h_b, nullptr, 0,
                           g_h0, H, B, H, mt * 128, nt * 64, 0, INSZ);
            } else if (u < 256) {
                int q = u - 64, mt = q / 48, nt = q % 48;
                jb = mkjob(g_decode, INSZ, wih0 + EMB, EMB + INSZ, bih0, nullptr, 0,
                           g_gi0c, H3, B, H3, mt * 128, nt * 64, 0, INSZ);
            } else if (u < 304) {
                int nt = u - 256;
                jb = mkjob(emb, EMB, wih0, EMB + INSZ, nullptr, nullptr, 0,
                           g_tokt, H3, V, H3, 0, nt * 64, 0, EMB);
            } else {
                int q = u - 304, mt = q >> 1, nt = q & 1;
                jb = mkjob(g_decode, INSZ, out_w + H, H + INSZ, out_b, nullptr, 0,
                           g_logc, V, B, V, mt * 128, nt * 64, 0, INSZ);
            }
            gemm_tile(jb, sAb, sWb);
        }
    }
    grid_bar();

    // ---- P3: broadcast h_init ----
    for (int idx = blockIdx.x * NTH + tid; idx < B * H; idx += gstride) {
        float v = g_h0[idx];
        g_h1[idx] = v;
        g_h2[idx] = v;
    }
    grid_bar();

    float* ghp[4] = {g_gh0, g_gh1, g_gh2, g_gh3};

    // ---- recurrent loop ----
    for (int t = 0; t < S; t++) {
        // A: gh(l0) k-split-4 (768) + logits(t-1) (8)
        {
            int U = 768 + (t > 0 ? 8 : 0);
            for (int u = blockIdx.x; u < U; u += nb) {
                Job jb;
                if (u < 768) {
                    int ks = u & 3, r = u >> 2, mt = r / 48, nt = r % 48;
                    jb = mkjob(g_h0, H, whh0, H, ks == 0 ? bhh0 : nullptr,
                               nullptr, 0, ghp[ks], H3, B, H3,
                               mt * 128, nt * 64, ks * 256, 256);
                } else {
                    int q = u - 768, nt = q & 1, mt = q >> 1;
                    jb = mkjob(g_h2, H, out_w, H + INSZ, nullptr, g_logc, V,
                               out + (size_t)(t - 1) * V, S * V, B, V,
                               mt * 128, nt * 64, 0, H);
                }
                gemm_tile(jb, sAb, sWb);
            }
        }
        grid_bar();

        // B: layer-0 GRU elementwise
        for (int idx = blockIdx.x * NTH + tid; idx < B * H; idx += gstride) {
            int b = idx >> 10, jx = idx & 1023;
            int tok = (t == 0) ? START_TOK : inputs[b * S + t - 1];
            const float* tr = g_tokt + (size_t)tok * H3;
            size_t b3 = (size_t)b * H3;
            float hr = g_gh0[b3 + jx] + g_gh1[b3 + jx] + g_gh2[b3 + jx] + g_gh3[b3 + jx];
            float hz = g_gh0[b3 + H + jx] + g_gh1[b3 + H + jx] + g_gh2[b3 + H + jx] + g_gh3[b3 + H + jx];
            float hn = g_gh0[b3 + 2 * H + jx] + g_gh1[b3 + 2 * H + jx] + g_gh2[b3 + 2 * H + jx] + g_gh3[b3 + 2 * H + jx];
            float ir = tr[jx] + g_gi0c[b3 + jx];
            float iz = tr[H + jx] + g_gi0c[b3 + H + jx];
            float in_ = tr[2 * H + jx] + g_gi0c[b3 + 2 * H + jx];
            float r  = sigm(ir + hr);
            float zz = sigm(iz + hz);
            float n  = tanhf(in_ + r * hn);
            g_h0[idx] = (1.0f - zz) * n + zz * g_h0[idx];
        }
        grid_bar();

        // C: layer-1 dual, k-split-2 (768)
        for (int u = blockIdx.x; u < 768; u += nb) {
            int ks = u & 1, r = u >> 1, mt = r / 48, nt = r % 48;
            Job jb;
            if (mt < 4)
                jb = mkjob(g_h0, H, wih1, H, ks == 0 ? bih1 : nullptr, nullptr, 0,
                           ks ? g_gi1 : g_gi0, H3, B, H3,
                           mt * 128, nt * 64, ks * 512, 512);
            else
                jb = mkjob(g_h1, H, whh1, H, ks == 0 ? bhh1 : nullptr, nullptr, 0,
                           ks ? g_gh1 : g_gh0, H3, B, H3,
                           (mt - 4) * 128, nt * 64, ks * 512, 512);
            gemm_tile(jb, sAb, sWb);
        }
        grid_bar();

        // D: layer-1 elementwise
        for (int idx = blockIdx.x * NTH + tid; idx < B * H; idx += gstride) {
            int b = idx >> 10, jx = idx & 1023;
            size_t b3 = (size_t)b * H3;
            float ir = g_gi0[b3 + jx] + g_gi1[b3 + jx];
            float iz = g_gi0[b3 + H + jx] + g_gi1[b3 + H + jx];
            float in_ = g_gi0[b3 + 2 * H + jx] + g_gi1[b3 + 2 * H + jx];
            float hr = g_gh0[b3 + jx] + g_gh1[b3 + jx];
            float hz = g_gh0[b3 + H + jx] + g_gh1[b3 + H + jx];
            float hn = g_gh0[b3 + 2 * H + jx] + g_gh1[b3 + 2 * H + jx];
            float r  = sigm(ir + hr);
            float zz = sigm(iz + hz);
            float n  = tanhf(in_ + r * hn);
            g_h1[idx] = (1.0f - zz) * n + zz * g_h1[idx];
        }
        grid_bar();

        // E: layer-2 dual, k-split-2 (768)
        for (int u = blockIdx.x; u < 768; u += nb) {
            int ks = u & 1, r = u >> 1, mt = r / 48, nt = r % 48;
            Job jb;
            if (mt < 4)
                jb = mkjob(g_h1, H, wih2, H, ks == 0 ? bih2 : nullptr, nullptr, 0,
                           ks ? g_gi1 : g_gi0, H3, B, H3,
                           mt * 128, nt * 64, ks * 512, 512);
            else
                jb = mkjob(g_h2, H, whh2, H, ks == 0 ? bhh2 : nullptr, nullptr, 0,
                           ks ? g_gh1 : g_gh0, H3, B, H3,
                           (mt - 4) * 128, nt * 64, ks * 512, 512);
            gemm_tile(jb, sAb, sWb);
        }
        grid_bar();

        // F: layer-2 elementwise
        for (int idx = blockIdx.x * NTH + tid; idx < B * H; idx += gstride) {
            int b = idx >> 10, jx = idx & 1023;
            size_t b3 = (size_t)b * H3;
            float ir = g_gi0[b3 + jx] + g_gi1[b3 + jx];
            float iz = g_gi0[b3 + H + jx] + g_gi1[b3 + H + jx];
            float in_ = g_gi0[b3 + 2 * H + jx] + g_gi1[b3 + 2 * H + jx];
            float hr = g_gh0[b3 + jx] + g_gh1[b3 + jx];
            float hz = g_gh0[b3 + H + jx] + g_gh1[b3 + H + jx];
            float hn = g_gh0[b3 + 2 * H + jx] + g_gh1[b3 + 2 * H + jx];
            float r  = sigm(ir + hr);
            float zz = sigm(iz + hz);
            float n  = tanhf(in_ + r * hn);
            g_h2[idx] = (1.0f - zz) * n + zz * g_h2[idx];
        }
        grid_bar();
    }

    // ---- final logits (t = S-1) ----
    for (int u = blockIdx.x; u < 8; u += nb) {
        int nt = u & 1, mt = u >> 1;
        Job jb = mkjob(g_h2, H, out_w, H + INSZ, nullptr, g_logc, V,
                       out + (size_t)(S - 1) * V, S * V, B, V,
                       mt * 128, nt * 64, 0, H);
        gemm_tile(jb, sAb, sWb);
    }
}

// ---------------- host ----------------
extern "C" void kernel_launch(void* const* d_in, const int* in_sizes, int n_in,
                              void* d_out, int out_size)
{
    (void)in_sizes; (void)n_in; (void)out_size;

    const int*   inputs = (const int*)  d_in[0];
    const float* z      = (const float*)d_in[1];
    const float* cond   = (const float*)d_in[2];
    const float* emb    = (const float*)d_in[4];
    const float* i2h_w  = (const float*)d_in[5];
    const float* i2h_b  = (const float*)d_in[6];
    const float* out_w  = (const float*)d_in[7];
    const float* out_b  = (const float*)d_in[8];
    const float* wih0 = (const float*)d_in[9];
    const float* whh0 = (const float*)d_in[10];
    const float* bih0 = (const float*)d_in[11];
    const float* bhh0 = (const float*)d_in[12];
    const float* wih1 = (const float*)d_in[13];
    const float* whh1 = (const float*)d_in[14];
    const float* bih1 = (const float*)d_in[15];
    const float* bhh1 = (const float*)d_in[16];
    const float* wih2 = (const float*)d_in[17];
    const float* whh2 = (const float*)d_in[18];
    const float* bih2 = (const float*)d_in[19];
    const float* bhh2 = (const float*)d_in[20];
    float* out = (float*)d_out;

    int dev = 0;
    cudaGetDevice(&dev);
    int sms = 148;
    cudaDeviceGetAttribute(&sms, cudaDevAttrMultiProcessorCount, dev);
    int bpm = 1;
    cudaOccupancyMaxActiveBlocksPerMultiprocessor(&bpm, decoder_k, NTH, 0);
    if (bpm < 1) bpm = 1;

    decoder_k<<<sms * bpm, NTH>>>(
        inputs, z, cond, emb, i2h_w, i2h_b, out_w, out_b,
        wih0, whh0, bih0, bhh0, wih1, whh1, bih1, bhh1,
        wih2, whh2, bih2, bhh2, out);
}

// round 6
// speedup vs baseline: 1.1597x; 1.1597x over previous
#include <cuda_runtime.h>
#include <cuda_bf16.h>
#include <cstdint>
#include <math.h>

#define B      512
#define S      200
#define H      1024
#define V      100
#define EMB    512
#define INSZ   1024
#define H3     3072
#define START_TOK 1
#define NTH    256

// dynamic smem layout (bytes); rows padded to 40 bf16 (80B) for conflict-free LDS
#define OFF_AH 0u
#define OFF_AL 10240u
#define OFF_WH 20480u
#define OFF_WL 35840u
#define SMEM_TOTAL 51200

// ---------------- fp32 scratch ----------------
__device__ float g_h0[B * H];
__device__ float g_h1[B * H];
__device__ float g_h2[B * H];
__device__ float g_gh0[B * H3];
__device__ float g_gh1[B * H3];
__device__ float g_gi[B * H3];
__device__ float g_gh[B * H3];
__device__ float g_gi0c[B * H3];
__device__ float g_tokt[V * H3];
__device__ float g_logc[B * V];
__device__ unsigned g_bar_count;
__device__ unsigned g_bar_phase;

// ---------------- bf16 hi/lo splits ----------------
__device__ __align__(16) __nv_bfloat16 g_whh0h[H3 * H], g_whh0l[H3 * H];
__device__ __align__(16) __nv_bfloat16 g_wih1h[H3 * H], g_wih1l[H3 * H];
__device__ __align__(16) __nv_bfloat16 g_whh1h[H3 * H], g_whh1l[H3 * H];
__device__ __align__(16) __nv_bfloat16 g_wih2h[H3 * H], g_wih2l[H3 * H];
__device__ __align__(16) __nv_bfloat16 g_whh2h[H3 * H], g_whh2l[H3 * H];
__device__ __align__(16) __nv_bfloat16 g_owh[128 * H],  g_owl[128 * H];
__device__ __align__(16) __nv_bfloat16 g_ow2h[128 * H], g_ow2l[128 * H];
__device__ __align__(16) __nv_bfloat16 g_i2hh[H * INSZ], g_i2hl[H * INSZ];
__device__ __align__(16) __nv_bfloat16 g_w0ah[H3 * EMB], g_w0al[H3 * EMB];
__device__ __align__(16) __nv_bfloat16 g_w0bh[H3 * H],   g_w0bl[H3 * H];
__device__ __align__(16) __nv_bfloat16 g_embh[128 * EMB], g_embl[128 * EMB];
__device__ __align__(16) __nv_bfloat16 g_dech[B * INSZ], g_decl[B * INSZ];
__device__ __align__(16) __nv_bfloat16 g_a0h[B * H], g_a0l[B * H];
__device__ __align__(16) __nv_bfloat16 g_a1h[B * H], g_a1l[B * H];
__device__ __align__(16) __nv_bfloat16 g_a2h[B * H], g_a2l[B * H];

// ---------------- grid barrier ----------------
__device__ __forceinline__ void grid_bar()
{
    __syncthreads();
    if (threadIdx.x == 0) {
        __threadfence();
        volatile unsigned* php = &g_bar_phase;
        unsigned ph = *php;
        if (atomicAdd(&g_bar_count, 1u) == gridDim.x - 1u) {
            g_bar_count = 0u;
            __threadfence();
            atomicAdd(&g_bar_phase, 1u);
        } else {
            while (*php == ph) { __nanosleep(32); }
        }
        __threadfence();
    }
    __syncthreads();
}

// ---------------- helpers ----------------
__device__ __forceinline__ float sigm(float x) { return 1.0f / (1.0f + __expf(-x)); }

__device__ __forceinline__ void bsplit(float x, __nv_bfloat16& hi, __nv_bfloat16& lo)
{
    hi = __float2bfloat16(x);
    lo = __float2bfloat16(x - __bfloat162float(hi));
}

__device__ __forceinline__ uint32_t lds32(uint32_t a)
{
    uint32_t v;
    asm volatile("ld.shared.b32 %0, [%1];" : "=r"(v) : "r"(a));
    return v;
}
__device__ __forceinline__ void sts128(uint32_t a, uint4 v)
{
    asm volatile("st.shared.v4.b32 [%0], {%1,%2,%3,%4};"
                 :: "r"(a), "r"(v.x), "r"(v.y), "r"(v.z), "r"(v.w) : "memory");
}
__device__ __forceinline__ void mma16816(float* d, const uint32_t* a, const uint32_t* b)
{
    asm volatile(
        "mma.sync.aligned.m16n8k16.row.col.f32.bf16.bf16.f32 "
        "{%0,%1,%2,%3}, {%4,%5,%6,%7}, {%8,%9}, {%0,%1,%2,%3};"
        : "+f"(d[0]), "+f"(d[1]), "+f"(d[2]), "+f"(d[3])
        : "r"(a[0]), "r"(a[1]), "r"(a[2]), "r"(a[3]), "r"(b[0]), "r"(b[1]));
}

// ---------------- GEMM unit: C[128, 32*NF] = A @ W^T via bf16x3 emu ----------------
struct MU {
    const __nv_bfloat16 *ah, *al, *wh, *wl;
    const float *bias, *cadd;
    float* C;
    int lda, ldw, ldadd, ldc, nch, mrows, ncols;
};

__device__ __forceinline__ MU mk_mu(
    const __nv_bfloat16* ah, const __nv_bfloat16* al, int lda,
    const __nv_bfloat16* wh, const __nv_bfloat16* wl, int ldw,
    const float* bias, const float* cadd, int ldadd,
    float* C, int ldc, int nch, int mrows, int ncols)
{
    MU u;
    u.ah = ah; u.al = al; u.wh = wh; u.wl = wl;
    u.bias = bias; u.cadd = cadd; u.C = C;
    u.lda = lda; u.ldw = ldw; u.ldadd = ldadd; u.ldc = ldc;
    u.nch = nch; u.mrows = mrows; u.ncols = ncols;
    return u;
}

template<int NF>
__device__ __noinline__ void mma_unit(const MU u, uint32_t smb)
{
    const int tid  = threadIdx.x;
    const int lane = tid & 31;
    const int w    = tid >> 5;
    const int wm   = w >> 2;            // 0..1
    const int wn   = w & 3;             // 0..3
    const int NW   = NF / 2;            // W uint4 iters (3 or 2)
    const int gq   = lane >> 2;         // group id 0..7
    const int tq   = lane & 3;          // 0..3

    float acc[4][NF][4];
#pragma unroll
    for (int i = 0; i < 4; i++)
#pragma unroll
        for (int j = 0; j < NF; j++)
#pragma unroll
            for (int k = 0; k < 4; k++) acc[i][j][k] = 0.0f;

    uint4 aR[2][2], wR[3][2];

#define LOADG(c) do { \
    _Pragma("unroll") for (int i = 0; i < 2; i++) { \
        int idx = tid + i * NTH; int r = idx >> 2, q = idx & 3; \
        const size_t go = (size_t)r * u.lda + (size_t)(c) * 32 + q * 8; \
        aR[i][0] = *reinterpret_cast<const uint4*>(u.ah + go); \
        aR[i][1] = *reinterpret_cast<const uint4*>(u.al + go); } \
    _Pragma("unroll") for (int i = 0; i < NW; i++) { \
        int idx = tid + i * NTH; int r = idx >> 2, q = idx & 3; \
        const size_t go = (size_t)r * u.ldw + (size_t)(c) * 32 + q * 8; \
        wR[i][0] = *reinterpret_cast<const uint4*>(u.wh + go); \
        wR[i][1] = *reinterpret_cast<const uint4*>(u.wl + go); } \
} while (0)

#define STSALL() do { \
    _Pragma("unroll") for (int i = 0; i < 2; i++) { \
        int idx = tid + i * NTH; int r = idx >> 2, q = idx & 3; \
        uint32_t off = (uint32_t)(r * 80 + q * 16); \
        sts128(smb + OFF_AH + off, aR[i][0]); \
        sts128(smb + OFF_AL + off, aR[i][1]); } \
    _Pragma("unroll") for (int i = 0; i < NW; i++) { \
        int idx = tid + i * NTH; int r = idx >> 2, q = idx & 3; \
        uint32_t off = (uint32_t)(r * 80 + q * 16); \
        sts128(smb + OFF_WH + off, wR[i][0]); \
        sts128(smb + OFF_WL + off, wR[i][1]); } \
} while (0)

    LOADG(0);
    for (int c = 0; c < u.nch; c++) {
        STSALL();
        __syncthreads();
        if (c + 1 < u.nch) LOADG(c + 1);

#pragma unroll
        for (int ks = 0; ks < 2; ks++) {
            const int kb = ks * 16;
            // B fragments for all NF n-tiles (hi & lo)
            uint32_t bh[NF][2], bl[NF][2];
#pragma unroll
            for (int nf = 0; nf < NF; nf++) {
                int n = wn * (NF * 8) + nf * 8 + gq;
                uint32_t off = (uint32_t)(n * 80 + (kb + 2 * tq) * 2);
                bh[nf][0] = lds32(smb + OFF_WH + off);
                bh[nf][1] = lds32(smb + OFF_WH + off + 16);
                bl[nf][0] = lds32(smb + OFF_WL + off);
                bl[nf][1] = lds32(smb + OFF_WL + off + 16);
            }
#pragma unroll
            for (int mf = 0; mf < 4; mf++) {
                int r = wm * 64 + mf * 16 + gq;
                uint32_t off = (uint32_t)(r * 80 + (kb + 2 * tq) * 2);
                uint32_t ah[4], al[4];
                ah[0] = lds32(smb + OFF_AH + off);
                ah[1] = lds32(smb + OFF_AH + off + 8 * 80);
                ah[2] = lds32(smb + OFF_AH + off + 16);
                ah[3] = lds32(smb + OFF_AH + off + 8 * 80 + 16);
                al[0] = lds32(smb + OFF_AL + off);
                al[1] = lds32(smb + OFF_AL + off + 8 * 80);
                al[2] = lds32(smb + OFF_AL + off + 16);
                al[3] = lds32(smb + OFF_AL + off + 8 * 80 + 16);
#pragma unroll
                for (int nf = 0; nf < NF; nf++) {
                    mma16816(acc[mf][nf], ah, bh[nf]);
                    mma16816(acc[mf][nf], ah, bl[nf]);
                    mma16816(acc[mf][nf], al, bh[nf]);
                }
            }
        }
        __syncthreads();
    }
#undef LOADG
#undef STSALL

    // epilogue
#pragma unroll
    for (int mf = 0; mf < 4; mf++) {
#pragma unroll
        for (int half = 0; half < 2; half++) {
            int m = wm * 64 + mf * 16 + gq + half * 8;
            if (m >= u.mrows) continue;
            float* crow = u.C + (size_t)m * u.ldc;
            const float* car = u.cadd ? u.cadd + (size_t)m * u.ldadd : nullptr;
#pragma unroll
            for (int nf = 0; nf < NF; nf++) {
#pragma unroll
                for (int e = 0; e < 2; e++) {
                    int col = wn * (NF * 8) + nf * 8 + 2 * tq + e;
                    if (col < u.ncols) {
                        float v = acc[mf][nf][half * 2 + e];
                        if (u.bias) v += u.bias[col];
                        if (car) v += car[col];
                        crow[col] = v;
                    }
                }
            }
        }
    }
}

// ---------------- persistent kernel ----------------
__global__ __launch_bounds__(NTH, 1) void decoder_k(
    const int* __restrict__ inputs, const float* __restrict__ z,
    const float* __restrict__ cond, const float* __restrict__ emb,
    const float* __restrict__ i2h_w, const float* __restrict__ i2h_b,
    const float* __restrict__ out_w, const float* __restrict__ out_b,
    const float* __restrict__ wih0, const float* __restrict__ whh0,
    const float* __restrict__ bih0, const float* __restrict__ bhh0,
    const float* __restrict__ wih1, const float* __restrict__ whh1,
    const float* __restrict__ bih1, const float* __restrict__ bhh1,
    const float* __restrict__ wih2, const float* __restrict__ whh2,
    const float* __restrict__ bih2, const float* __restrict__ bhh2,
    float* __restrict__ out)
{
    extern __shared__ __align__(16) char smem[];
    uint32_t smb;
    asm("{ .reg .u64 t; cvta.to.shared.u64 t, %1; cvt.u32.u64 %0, t; }"
        : "=r"(smb) : "l"(smem));

    const int tid = threadIdx.x;
    const unsigned nb = gridDim.x;
    const int gid = blockIdx.x * NTH + tid;
    const int gstride = nb * NTH;

    // ---- P0: operand splits ----
    {
        const float* ws[5] = {whh0, wih1, whh1, wih2, whh2};
        __nv_bfloat16* wh_[5] = {g_whh0h, g_wih1h, g_whh1h, g_wih2h, g_whh2h};
        __nv_bfloat16* wl_[5] = {g_whh0l, g_wih1l, g_whh1l, g_wih2l, g_whh2l};
        for (int s = 0; s < 5; s++)
            for (int i = gid; i < H3 * H; i += gstride)
                bsplit(ws[s][i], wh_[s][i], wl_[s][i]);
    }
    for (int i = gid; i < H * INSZ; i += gstride) bsplit(i2h_w[i], g_i2hh[i], g_i2hl[i]);
    for (int i = gid; i < H3 * EMB; i += gstride) {
        int r = i >> 9, c = i & 511;
        bsplit(wih0[(size_t)r * (EMB + INSZ) + c], g_w0ah[i], g_w0al[i]);
    }
    for (int i = gid; i < H3 * H; i += gstride) {
        int r = i >> 10, c = i & 1023;
        bsplit(wih0[(size_t)r * (EMB + INSZ) + EMB + c], g_w0bh[i], g_w0bl[i]);
    }
    for (int i = gid; i < 128 * EMB; i += gstride) {
        int r = i >> 9, c = i & 511;
        bsplit(r < V ? emb[r * EMB + c] : 0.0f, g_embh[i], g_embl[i]);
    }
    for (int i = gid; i < 128 * H; i += gstride) {
        int r = i >> 10, c = i & 1023;
        bsplit(r < V ? out_w[(size_t)r * (H + INSZ) + c] : 0.0f, g_owh[i], g_owl[i]);
        bsplit(r < V ? out_w[(size_t)r * (H + INSZ) + H + c] : 0.0f, g_ow2h[i], g_ow2l[i]);
    }
    for (int i = gid; i < B * INSZ; i += gstride) {
        int b = i >> 10, jx = i & 1023;
        float v = (jx < 512) ? z[b * 512 + jx] : cond[b * 512 + jx - 512];
        bsplit(v, g_dech[i], g_decl[i]);
    }
    grid_bar();

    // ---- P2: prologue GEMMs (116 units) ----
    for (int u = blockIdx.x; u < 116; u += nb) {
        if (u < 32) {            // h_init [512,1024,1024] NF4
            int mt = u & 3, nt = u >> 2;
            mma_unit<4>(mk_mu(
                g_dech + (size_t)(mt * 128) * INSZ, g_decl + (size_t)(mt * 128) * INSZ, INSZ,
                g_i2hh + (size_t)(nt * 128) * INSZ, g_i2hl + (size_t)(nt * 128) * INSZ, INSZ,
                i2h_b + nt * 128, nullptr, 0,
                g_h0 + (size_t)(mt * 128) * H + nt * 128, H, 32, 128, 128), smb);
        } else if (u < 96) {     // gi0c [512,3072,1024] NF6
            int q = u - 32, mt = q & 3, nt = q >> 2;
            mma_unit<6>(mk_mu(
                g_dech + (size_t)(mt * 128) * INSZ, g_decl + (size_t)(mt * 128) * INSZ, INSZ,
                g_w0bh + (size_t)(nt * 192) * H, g_w0bl + (size_t)(nt * 192) * H, H,
                bih0 + nt * 192, nullptr, 0,
                g_gi0c + (size_t)(mt * 128) * H3 + nt * 192, H3, 32, 128, 192), smb);
        } else if (u < 112) {    // tokt [100,3072,512] NF6
            int nt = u - 96;
            mma_unit<6>(mk_mu(
                g_embh, g_embl, EMB,
                g_w0ah + (size_t)(nt * 192) * EMB, g_w0al + (size_t)(nt * 192) * EMB, EMB,
                nullptr, nullptr, 0,
                g_tokt + nt * 192, H3, 16, V, 192), smb);
        } else {                 // logc [512,100,1024] NF4
            int mt = u - 112;
            mma_unit<4>(mk_mu(
                g_dech + (size_t)(mt * 128) * INSZ, g_decl + (size_t)(mt * 128) * INSZ, INSZ,
                g_ow2h, g_ow2l, H,
                out_b, nullptr, 0,
                g_logc + (size_t)(mt * 128) * V, V, 32, 128, V), smb);
        }
    }
    grid_bar();

    // ---- P3: broadcast h_init + splits ----
    for (int i = gid; i < B * H; i += gstride) {
        float v = g_h0[i];
        g_h1[i] = v; g_h2[i] = v;
        __nv_bfloat16 hi, lo;
        bsplit(v, hi, lo);
        g_a0h[i] = hi; g_a0l[i] = lo;
        g_a1h[i] = hi; g_a1l[i] = lo;
        g_a2h[i] = hi; g_a2l[i] = lo;
    }
    grid_bar();

    // ---- recurrent loop ----
    for (int t = 0; t < S; t++) {
        // A: gh(l0) k-split-2 (128 units NF6) + logits(t-1) (4 units NF4)
        {
            const int U = 128 + (t > 0 ? 4 : 0);
            for (int u = blockIdx.x; u < U; u += nb) {
                if (u < 128) {
                    int ks = u & 1, r = u >> 1, mt = r & 3, nt = r >> 2;
                    mma_unit<6>(mk_mu(
                        g_a0h + (size_t)(mt * 128) * H + ks * 512,
                        g_a0l + (size_t)(mt * 128) * H + ks * 512, H,
                        g_whh0h + (size_t)(nt * 192) * H + ks * 512,
                        g_whh0l + (size_t)(nt * 192) * H + ks * 512, H,
                        ks == 0 ? bhh0 + nt * 192 : nullptr, nullptr, 0,
                        (ks ? g_gh1 : g_gh0) + (size_t)(mt * 128) * H3 + nt * 192,
                        H3, 16, 128, 192), smb);
                } else {
                    int mt = u - 128;
                    mma_unit<4>(mk_mu(
                        g_a2h + (size_t)(mt * 128) * H, g_a2l + (size_t)(mt * 128) * H, H,
                        g_owh, g_owl, H,
                        nullptr, g_logc + (size_t)(mt * 128) * V, V,
                        out + (size_t)(mt * 128) * (S * V) + (size_t)(t - 1) * V,
                        S * V, 32, 128, V), smb);
                }
            }
        }
        grid_bar();

        // B: layer-0 GRU elementwise + split
        for (int i = gid; i < B * H; i += gstride) {
            int b = i >> 10, jx = i & 1023;
            int tok = (t == 0) ? START_TOK : inputs[b * S + t - 1];
            const float* tr = g_tokt + (size_t)tok * H3;
            size_t b3 = (size_t)b * H3;
            float hr = g_gh0[b3 + jx] + g_gh1[b3 + jx];
            float hz = g_gh0[b3 + H + jx] + g_gh1[b3 + H + jx];
            float hn = g_gh0[b3 + 2 * H + jx] + g_gh1[b3 + 2 * H + jx];
            float ir = tr[jx] + g_gi0c[b3 + jx];
            float iz = tr[H + jx] + g_gi0c[b3 + H + jx];
            float in_ = tr[2 * H + jx] + g_gi0c[b3 + 2 * H + jx];
            float r = sigm(ir + hr), zz = sigm(iz + hz);
            float n = tanhf(in_ + r * hn);
            float hv = (1.0f - zz) * n + zz * g_h0[i];
            g_h0[i] = hv;
            bsplit(hv, g_a0h[i], g_a0l[i]);
        }
        grid_bar();

        // C: layer-1 dual (128 units NF6)
        for (int u = blockIdx.x; u < 128; u += nb) {
            int q = u & 63, mt = q & 3, nt = q >> 2;
            if (u < 64)
                mma_unit<6>(mk_mu(
                    g_a0h + (size_t)(mt * 128) * H, g_a0l + (size_t)(mt * 128) * H, H,
                    g_wih1h + (size_t)(nt * 192) * H, g_wih1l + (size_t)(nt * 192) * H, H,
                    bih1 + nt * 192, nullptr, 0,
                    g_gi + (size_t)(mt * 128) * H3 + nt * 192, H3, 32, 128, 192), smb);
            else
                mma_unit<6>(mk_mu(
                    g_a1h + (size_t)(mt * 128) * H, g_a1l + (size_t)(mt * 128) * H, H,
                    g_whh1h + (size_t)(nt * 192) * H, g_whh1l + (size_t)(nt * 192) * H, H,
                    bhh1 + nt * 192, nullptr, 0,
                    g_gh + (size_t)(mt * 128) * H3 + nt * 192, H3, 32, 128, 192), smb);
        }
        grid_bar();

        // D: layer-1 elementwise + split
        for (int i = gid; i < B * H; i += gstride) {
            int b = i >> 10, jx = i & 1023;
            size_t b3 = (size_t)b * H3;
            float r = sigm(g_gi[b3 + jx] + g_gh[b3 + jx]);
            float zz = sigm(g_gi[b3 + H + jx] + g_gh[b3 + H + jx]);
            float n = tanhf(g_gi[b3 + 2 * H + jx] + r * g_gh[b3 + 2 * H + jx]);
            float hv = (1.0f - zz) * n + zz * g_h1[i];
            g_h1[i] = hv;
            bsplit(hv, g_a1h[i], g_a1l[i]);
        }
        grid_bar();

        // E: layer-2 dual (128 units NF6)
        for (int u = blockIdx.x; u < 128; u += nb) {
            int q = u & 63, mt = q & 3, nt = q >> 2;
            if (u < 64)
                mma_unit<6>(mk_mu(
                    g_a1h + (size_t)(mt * 128) * H, g_a1l + (size_t)(mt * 128) * H, H,
                    g_wih2h + (size_t)(nt * 192) * H, g_wih2l + (size_t)(nt * 192) * H, H,
                    bih2 + nt * 192, nullptr, 0,
                    g_gi + (size_t)(mt * 128) * H3 + nt * 192, H3, 32, 128, 192), smb);
            else
                mma_unit<6>(mk_mu(
                    g_a2h + (size_t)(mt * 128) * H, g_a2l + (size_t)(mt * 128) * H, H,
                    g_whh2h + (size_t)(nt * 192) * H, g_whh2l + (size_t)(nt * 192) * H, H,
                    bhh2 + nt * 192, nullptr, 0,
                    g_gh + (size_t)(mt * 128) * H3 + nt * 192, H3, 32, 128, 192), smb);
        }
        grid_bar();

        // F: layer-2 elementwise + split
        for (int i = gid; i < B * H; i += gstride) {
            int b = i >> 10, jx = i & 1023;
            size_t b3 = (size_t)b * H3;
            float r = sigm(g_gi[b3 + jx] + g_gh[b3 + jx]);
            float zz = sigm(g_gi[b3 + H + jx] + g_gh[b3 + H + jx]);
            float n = tanhf(g_gi[b3 + 2 * H + jx] + r * g_gh[b3 + 2 * H + jx]);
            float hv = (1.0f - zz) * n + zz * g_h2[i];
            g_h2[i] = hv;
            bsplit(hv, g_a2h[i], g_a2l[i]);
        }
        grid_bar();
    }

    // ---- final logits (t = S-1) ----
    for (int u = blockIdx.x; u < 4; u += nb) {
        int mt = u;
        mma_unit<4>(mk_mu(
            g_a2h + (size_t)(mt * 128) * H, g_a2l + (size_t)(mt * 128) * H, H,
            g_owh, g_owl, H,
            nullptr, g_logc + (size_t)(mt * 128) * V, V,
            out + (size_t)(mt * 128) * (S * V) + (size_t)(S - 1) * V,
            S * V, 32, 128, V), smb);
    }
}

// ---------------- host ----------------
extern "C" void kernel_launch(void* const* d_in, const int* in_sizes, int n_in,
                              void* d_out, int out_size)
{
    (void)in_sizes; (void)n_in; (void)out_size;

    const int*   inputs = (const int*)  d_in[0];
    const float* z      = (const float*)d_in[1];
    const float* cond   = (const float*)d_in[2];
    const float* emb    = (const float*)d_in[4];
    const float* i2h_w  = (const float*)d_in[5];
    const float* i2h_b  = (const float*)d_in[6];
    const float* out_w  = (const float*)d_in[7];
    const float* out_b  = (const float*)d_in[8];
    const float* wih0 = (const float*)d_in[9];
    const float* whh0 = (const float*)d_in[10];
    const float* bih0 = (const float*)d_in[11];
    const float* bhh0 = (const float*)d_in[12];
    const float* wih1 = (const float*)d_in[13];
    const float* whh1 = (const float*)d_in[14];
    const float* bih1 = (const float*)d_in[15];
    const float* bhh1 = (const float*)d_in[16];
    const float* wih2 = (const float*)d_in[17];
    const float* whh2 = (const float*)d_in[18];
    const float* bih2 = (const float*)d_in[19];
    const float* bhh2 = (const float*)d_in[20];
    float* out = (float*)d_out;

    cudaFuncSetAttribute(decoder_k, cudaFuncAttributeMaxDynamicSharedMemorySize,
                         SMEM_TOTAL);

    int dev = 0;
    cudaGetDevice(&dev);
    int sms = 148;
    cudaDeviceGetAttribute(&sms, cudaDevAttrMultiProcessorCount, dev);
    int bpm = 1;
    cudaOccupancyMaxActiveBlocksPerMultiprocessor(&bpm, decoder_k, NTH, SMEM_TOTAL);
    if (bpm < 1) bpm = 1;

    decoder_k<<<sms * bpm, NTH, SMEM_TOTAL>>>(
        inputs, z, cond, emb, i2h_w, i2h_b, out_w, out_b,
        wih0, whh0, bih0, bhh0, wih1, whh1, bih1, bhh1,
        wih2, whh2, bih2, bhh2, out);
}

// round 7
// speedup vs baseline: 1.9491x; 1.6807x over previous
#include <cuda_runtime.h>
#include <cuda_bf16.h>
#include <cstdint>
#include <math.h>

#define B      512
#define S      200
#define H      1024
#define V      100
#define EMB    512
#define INSZ   1024
#define H3     3072
#define START_TOK 1
#define NTH    512

// smem per buffer (bytes); rows padded to 40 bf16 (80B) for conflict-free LDS
#define OFF_AH 0u
#define OFF_AL 10240u
#define OFF_WH 20480u
#define OFF_WL 35840u
#define BUFSTRIDE 51200u
#define SMEM_TOTAL 102400

// ---------------- fp32 scratch ----------------
__device__ float g_h0[B * H];
__device__ float g_h1[B * H];
__device__ float g_h2[B * H];
__device__ float g_gh0[B * H3];
__device__ float g_gh1[B * H3];
__device__ float g_gi[B * H3];
__device__ float g_gh[B * H3];
__device__ float g_gi0c[B * H3];
__device__ float g_tokt[V * H3];
__device__ float g_logc[B * V];
__device__ unsigned g_bar_count;
__device__ unsigned g_bar_phase;

// ---------------- bf16 hi/lo splits ----------------
__device__ __align__(16) __nv_bfloat16 g_whh0h[H3 * H], g_whh0l[H3 * H];
__device__ __align__(16) __nv_bfloat16 g_wih1h[H3 * H], g_wih1l[H3 * H];
__device__ __align__(16) __nv_bfloat16 g_whh1h[H3 * H], g_whh1l[H3 * H];
__device__ __align__(16) __nv_bfloat16 g_wih2h[H3 * H], g_wih2l[H3 * H];
__device__ __align__(16) __nv_bfloat16 g_whh2h[H3 * H], g_whh2l[H3 * H];
__device__ __align__(16) __nv_bfloat16 g_owh[128 * H],  g_owl[128 * H];
__device__ __align__(16) __nv_bfloat16 g_ow2h[128 * H], g_ow2l[128 * H];
__device__ __align__(16) __nv_bfloat16 g_i2hh[H * INSZ], g_i2hl[H * INSZ];
__device__ __align__(16) __nv_bfloat16 g_w0ah[H3 * EMB], g_w0al[H3 * EMB];
__device__ __align__(16) __nv_bfloat16 g_w0bh[H3 * H],   g_w0bl[H3 * H];
__device__ __align__(16) __nv_bfloat16 g_embh[128 * EMB], g_embl[128 * EMB];
__device__ __align__(16) __nv_bfloat16 g_dech[B * INSZ], g_decl[B * INSZ];
__device__ __align__(16) __nv_bfloat16 g_a0h[B * H], g_a0l[B * H];
__device__ __align__(16) __nv_bfloat16 g_a1h[B * H], g_a1l[B * H];
__device__ __align__(16) __nv_bfloat16 g_a2h[B * H], g_a2l[B * H];

// ---------------- grid barrier ----------------
__device__ __forceinline__ void grid_bar()
{
    __syncthreads();
    if (threadIdx.x == 0) {
        __threadfence();
        volatile unsigned* php = &g_bar_phase;
        unsigned ph = *php;
        if (atomicAdd(&g_bar_count, 1u) == gridDim.x - 1u) {
            g_bar_count = 0u;
            __threadfence();
            atomicAdd(&g_bar_phase, 1u);
        } else {
            while (*php == ph) { __nanosleep(32); }
        }
        __threadfence();
    }
    __syncthreads();
}

// ---------------- helpers ----------------
__device__ __forceinline__ float sigm(float x) { return 1.0f / (1.0f + __expf(-x)); }

__device__ __forceinline__ void bsplit(float x, __nv_bfloat16& hi, __nv_bfloat16& lo)
{
    hi = __float2bfloat16(x);
    lo = __float2bfloat16(x - __bfloat162float(hi));
}

__device__ __forceinline__ uint32_t lds32(uint32_t a)
{
    uint32_t v;
    asm volatile("ld.shared.b32 %0, [%1];" : "=r"(v) : "r"(a));
    return v;
}
__device__ __forceinline__ void sts128(uint32_t a, uint4 v)
{
    asm volatile("st.shared.v4.b32 [%0], {%1,%2,%3,%4};"
                 :: "r"(a), "r"(v.x), "r"(v.y), "r"(v.z), "r"(v.w) : "memory");
}
__device__ __forceinline__ void mma16816(float* d, const uint32_t* a, const uint32_t* b)
{
    asm volatile(
        "mma.sync.aligned.m16n8k16.row.col.f32.bf16.bf16.f32 "
        "{%0,%1,%2,%3}, {%4,%5,%6,%7}, {%8,%9}, {%0,%1,%2,%3};"
        : "+f"(d[0]), "+f"(d[1]), "+f"(d[2]), "+f"(d[3])
        : "r"(a[0]), "r"(a[1]), "r"(a[2]), "r"(a[3]), "r"(b[0]), "r"(b[1]));
}

// ---------------- GEMM unit: C[128, 32*NF] = A @ W^T via bf16x3 emu ----------------
struct MU {
    const __nv_bfloat16 *ah, *al, *wh, *wl;
    const float *bias, *cadd;
    float* C;
    int lda, ldw, ldadd, ldc, nch, mrows, ncols;
};

__device__ __forceinline__ MU mk_mu(
    const __nv_bfloat16* ah, const __nv_bfloat16* al, int lda,
    const __nv_bfloat16* wh, const __nv_bfloat16* wl, int ldw,
    const float* bias, const float* cadd, int ldadd,
    float* C, int ldc, int nch, int mrows, int ncols)
{
    MU u;
    u.ah = ah; u.al = al; u.wh = wh; u.wl = wl;
    u.bias = bias; u.cadd = cadd; u.C = C;
    u.lda = lda; u.ldw = ldw; u.ldadd = ldadd; u.ldc = ldc;
    u.nch = nch; u.mrows = mrows; u.ncols = ncols;
    return u;
}

// 512 threads = 16 warps: 4m x 4n. Each warp: 32 rows (mf=2 x m16) x NF*8 cols.
template<int NF>
__device__ __noinline__ void mma_unit(const MU u, uint32_t smb)
{
    const int tid  = threadIdx.x;
    const int lane = tid & 31;
    const int w    = tid >> 5;
    const int wm   = w >> 2;            // 0..3  (32 rows each)
    const int wn   = w & 3;             // 0..3  (NF*8 cols each)
    const int gq   = lane >> 2;         // 0..7
    const int tq   = lane & 3;          // 0..3

    float acc[2][NF][4];
#pragma unroll
    for (int i = 0; i < 2; i++)
#pragma unroll
        for (int j = 0; j < NF; j++)
#pragma unroll
            for (int k = 0; k < 4; k++) acc[i][j][k] = 0.0f;

    // loaders: A = 512 uint4 (1/thread), W = NF*128 uint4 (iter0 all, iter1 if NF==6 for tid<256)
    const int ar = tid >> 2, aq = tid & 3;
    const bool w2 = (NF == 6) && (tid < 256);
    uint4 aR[2], wR0[2], wR1[2];

#define LOADG(c) do { \
    { const size_t go = (size_t)ar * u.lda + (size_t)(c) * 32 + aq * 8; \
      aR[0] = *reinterpret_cast<const uint4*>(u.ah + go); \
      aR[1] = *reinterpret_cast<const uint4*>(u.al + go); } \
    { const size_t go = (size_t)ar * u.ldw + (size_t)(c) * 32 + aq * 8; \
      wR0[0] = *reinterpret_cast<const uint4*>(u.wh + go); \
      wR0[1] = *reinterpret_cast<const uint4*>(u.wl + go); } \
    if (w2) { int idx = tid + 512; int r = idx >> 2, q = idx & 3; \
      const size_t go = (size_t)r * u.ldw + (size_t)(c) * 32 + q * 8; \
      wR1[0] = *reinterpret_cast<const uint4*>(u.wh + go); \
      wR1[1] = *reinterpret_cast<const uint4*>(u.wl + go); } \
} while (0)

#define STSALL(buf) do { \
    const uint32_t bb = smb + (buf) * BUFSTRIDE; \
    { uint32_t off = (uint32_t)(ar * 80 + aq * 16); \
      sts128(bb + OFF_AH + off, aR[0]); \
      sts128(bb + OFF_AL + off, aR[1]); \
      sts128(bb + OFF_WH + off, wR0[0]); \
      sts128(bb + OFF_WL + off, wR0[1]); } \
    if (w2) { int idx = tid + 512; int r = idx >> 2, q = idx & 3; \
      uint32_t off = (uint32_t)(r * 80 + q * 16); \
      sts128(bb + OFF_WH + off, wR1[0]); \
      sts128(bb + OFF_WL + off, wR1[1]); } \
} while (0)

    LOADG(0);
    STSALL(0);
    __syncthreads();

    for (int c = 0; c < u.nch; c++) {
        if (c + 1 < u.nch) LOADG(c + 1);

        const uint32_t bb = smb + (uint32_t)(c & 1) * BUFSTRIDE;
#pragma unroll
        for (int ks = 0; ks < 2; ks++) {
            const int kb = ks * 16;
            uint32_t bh[NF][2], bl[NF][2];
#pragma unroll
            for (int nf = 0; nf < NF; nf++) {
                int n = wn * (NF * 8) + nf * 8 + gq;
                uint32_t off = (uint32_t)(n * 80 + (kb + 2 * tq) * 2);
                bh[nf][0] = lds32(bb + OFF_WH + off);
                bh[nf][1] = lds32(bb + OFF_WH + off + 16);
                bl[nf][0] = lds32(bb + OFF_WL + off);
                bl[nf][1] = lds32(bb + OFF_WL + off + 16);
            }
#pragma unroll
            for (int mf = 0; mf < 2; mf++) {
                int r = wm * 32 + mf * 16 + gq;
                uint32_t off = (uint32_t)(r * 80 + (kb + 2 * tq) * 2);
                uint32_t ah[4], al[4];
                ah[0] = lds32(bb + OFF_AH + off);
                ah[1] = lds32(bb + OFF_AH + off + 8 * 80);
                ah[2] = lds32(bb + OFF_AH + off + 16);
                ah[3] = lds32(bb + OFF_AH + off + 8 * 80 + 16);
                al[0] = lds32(bb + OFF_AL + off);
                al[1] = lds32(bb + OFF_AL + off + 8 * 80);
                al[2] = lds32(bb + OFF_AL + off + 16);
                al[3] = lds32(bb + OFF_AL + off + 8 * 80 + 16);
#pragma unroll
                for (int nf = 0; nf < NF; nf++) {
                    mma16816(acc[mf][nf], ah, bh[nf]);
                    mma16816(acc[mf][nf], ah, bl[nf]);
                    mma16816(acc[mf][nf], al, bh[nf]);
                }
            }
        }

        if (c + 1 < u.nch) {
            STSALL((c + 1) & 1);
        }
        __syncthreads();
    }
#undef LOADG
#undef STSALL

    // epilogue
#pragma unroll
    for (int mf = 0; mf < 2; mf++) {
#pragma unroll
        for (int half = 0; half < 2; half++) {
            int m = wm * 32 + mf * 16 + gq + half * 8;
            if (m >= u.mrows) continue;
            float* crow = u.C + (size_t)m * u.ldc;
            const float* car = u.cadd ? u.cadd + (size_t)m * u.ldadd : nullptr;
#pragma unroll
            for (int nf = 0; nf < NF; nf++) {
#pragma unroll
                for (int e = 0; e < 2; e++) {
                    int col = wn * (NF * 8) + nf * 8 + 2 * tq + e;
                    if (col < u.ncols) {
                        float v = acc[mf][nf][half * 2 + e];
                        if (u.bias) v += u.bias[col];
                        if (car) v += car[col];
                        crow[col] = v;
                    }
                }
            }
        }
    }
    __syncthreads();
}

// ---------------- persistent kernel ----------------
__global__ __launch_bounds__(NTH, 1) void decoder_k(
    const int* __restrict__ inputs, const float* __restrict__ z,
    const float* __restrict__ cond, const float* __restrict__ emb,
    const float* __restrict__ i2h_w, const float* __restrict__ i2h_b,
    const float* __restrict__ out_w, const float* __restrict__ out_b,
    const float* __restrict__ wih0, const float* __restrict__ whh0,
    const float* __restrict__ bih0, const float* __restrict__ bhh0,
    const float* __restrict__ wih1, const float* __restrict__ whh1,
    const float* __restrict__ bih1, const float* __restrict__ bhh1,
    const float* __restrict__ wih2, const float* __restrict__ whh2,
    const float* __restrict__ bih2, const float* __restrict__ bhh2,
    float* __restrict__ out)
{
    extern __shared__ __align__(16) char smem[];
    uint32_t smb;
    asm("{ .reg .u64 t; cvta.to.shared.u64 t, %1; cvt.u32.u64 %0, t; }"
        : "=r"(smb) : "l"(smem));

    const int tid = threadIdx.x;
    const unsigned nb = gridDim.x;
    const int gid = blockIdx.x * NTH + tid;
    const int gstride = nb * NTH;

    // ---- P0: operand splits ----
    {
        const float* ws[5] = {whh0, wih1, whh1, wih2, whh2};
        __nv_bfloat16* wh_[5] = {g_whh0h, g_wih1h, g_whh1h, g_wih2h, g_whh2h};
        __nv_bfloat16* wl_[5] = {g_whh0l, g_wih1l, g_whh1l, g_wih2l, g_whh2l};
        for (int s = 0; s < 5; s++)
            for (int i = gid; i < H3 * H; i += gstride)
                bsplit(ws[s][i], wh_[s][i], wl_[s][i]);
    }
    for (int i = gid; i < H * INSZ; i += gstride) bsplit(i2h_w[i], g_i2hh[i], g_i2hl[i]);
    for (int i = gid; i < H3 * EMB; i += gstride) {
        int r = i >> 9, c = i & 511;
        bsplit(wih0[(size_t)r * (EMB + INSZ) + c], g_w0ah[i], g_w0al[i]);
    }
    for (int i = gid; i < H3 * H; i += gstride) {
        int r = i >> 10, c = i & 1023;
        bsplit(wih0[(size_t)r * (EMB + INSZ) + EMB + c], g_w0bh[i], g_w0bl[i]);
    }
    for (int i = gid; i < 128 * EMB; i += gstride) {
        int r = i >> 9, c = i & 511;
        bsplit(r < V ? emb[r * EMB + c] : 0.0f, g_embh[i], g_embl[i]);
    }
    for (int i = gid; i < 128 * H; i += gstride) {
        int r = i >> 10, c = i & 1023;
        bsplit(r < V ? out_w[(size_t)r * (H + INSZ) + c] : 0.0f, g_owh[i], g_owl[i]);
        bsplit(r < V ? out_w[(size_t)r * (H + INSZ) + H + c] : 0.0f, g_ow2h[i], g_ow2l[i]);
    }
    for (int i = gid; i < B * INSZ; i += gstride) {
        int b = i >> 10, jx = i & 1023;
        float v = (jx < 512) ? z[b * 512 + jx] : cond[b * 512 + jx - 512];
        bsplit(v, g_dech[i], g_decl[i]);
    }
    grid_bar();

    // ---- P2: prologue GEMMs (116 units) ----
    for (int u = blockIdx.x; u < 116; u += nb) {
        if (u < 32) {            // h_init [512,1024,1024] NF4
            int mt = u & 3, nt = u >> 2;
            mma_unit<4>(mk_mu(
                g_dech + (size_t)(mt * 128) * INSZ, g_decl + (size_t)(mt * 128) * INSZ, INSZ,
                g_i2hh + (size_t)(nt * 128) * INSZ, g_i2hl + (size_t)(nt * 128) * INSZ, INSZ,
                i2h_b + nt * 128, nullptr, 0,
                g_h0 + (size_t)(mt * 128) * H + nt * 128, H, 32, 128, 128), smb);
        } else if (u < 96) {     // gi0c [512,3072,1024] NF6
            int q = u - 32, mt = q & 3, nt = q >> 2;
            mma_unit<6>(mk_mu(
                g_dech + (size_t)(mt * 128) * INSZ, g_decl + (size_t)(mt * 128) * INSZ, INSZ,
                g_w0bh + (size_t)(nt * 192) * H, g_w0bl + (size_t)(nt * 192) * H, H,
                bih0 + nt * 192, nullptr, 0,
                g_gi0c + (size_t)(mt * 128) * H3 + nt * 192, H3, 32, 128, 192), smb);
        } else if (u < 112) {    // tokt [100,3072,512] NF6
            int nt = u - 96;
            mma_unit<6>(mk_mu(
                g_embh, g_embl, EMB,
                g_w0ah + (size_t)(nt * 192) * EMB, g_w0al + (size_t)(nt * 192) * EMB, EMB,
                nullptr, nullptr, 0,
                g_tokt + nt * 192, H3, 16, V, 192), smb);
        } else {                 // logc [512,100,1024] NF4
            int mt = u - 112;
            mma_unit<4>(mk_mu(
                g_dech + (size_t)(mt * 128) * INSZ, g_decl + (size_t)(mt * 128) * INSZ, INSZ,
                g_ow2h, g_ow2l, H,
                out_b, nullptr, 0,
                g_logc + (size_t)(mt * 128) * V, V, 32, 128, V), smb);
        }
    }
    grid_bar();

    // ---- P3: broadcast h_init + splits ----
    for (int i = gid; i < B * H; i += gstride) {
        float v = g_h0[i];
        g_h1[i] = v; g_h2[i] = v;
        __nv_bfloat16 hi, lo;
        bsplit(v, hi, lo);
        g_a0h[i] = hi; g_a0l[i] = lo;
        g_a1h[i] = hi; g_a1l[i] = lo;
        g_a2h[i] = hi; g_a2l[i] = lo;
    }
    grid_bar();

    // ---- recurrent loop ----
    for (int t = 0; t < S; t++) {
        // A: gh(l0) k-split-2 (128 units NF6) + logits(t-1) (4 units NF4)
        {
            const int U = 128 + (t > 0 ? 4 : 0);
            for (int u = blockIdx.x; u < U; u += nb) {
                if (u < 128) {
                    int ks = u & 1, r = u >> 1, mt = r & 3, nt = r >> 2;
                    mma_unit<6>(mk_mu(
                        g_a0h + (size_t)(mt * 128) * H + ks * 512,
                        g_a0l + (size_t)(mt * 128) * H + ks * 512, H,
                        g_whh0h + (size_t)(nt * 192) * H + ks * 512,
                        g_whh0l + (size_t)(nt * 192) * H + ks * 512, H,
                        ks == 0 ? bhh0 + nt * 192 : nullptr, nullptr, 0,
                        (ks ? g_gh1 : g_gh0) + (size_t)(mt * 128) * H3 + nt * 192,
                        H3, 16, 128, 192), smb);
                } else {
                    int mt = u - 128;
                    mma_unit<4>(mk_mu(
                        g_a2h + (size_t)(mt * 128) * H, g_a2l + (size_t)(mt * 128) * H, H,
                        g_owh, g_owl, H,
                        nullptr, g_logc + (size_t)(mt * 128) * V, V,
                        out + (size_t)(mt * 128) * (S * V) + (size_t)(t - 1) * V,
                        S * V, 32, 128, V), smb);
                }
            }
        }
        grid_bar();

        // B: layer-0 GRU elementwise + split
        for (int i = gid; i < B * H; i += gstride) {
            int b = i >> 10, jx = i & 1023;
            int tok = (t == 0) ? START_TOK : inputs[b * S + t - 1];
            const float* tr = g_tokt + (size_t)tok * H3;
            size_t b3 = (size_t)b * H3;
            float hr = g_gh0[b3 + jx] + g_gh1[b3 + jx];
            float hz = g_gh0[b3 + H + jx] + g_gh1[b3 + H + jx];
            float hn = g_gh0[b3 + 2 * H + jx] + g_gh1[b3 + 2 * H + jx];
            float ir = tr[jx] + g_gi0c[b3 + jx];
            float iz = tr[H + jx] + g_gi0c[b3 + H + jx];
            float in_ = tr[2 * H + jx] + g_gi0c[b3 + 2 * H + jx];
            float r = sigm(ir + hr), zz = sigm(iz + hz);
            float n = tanhf(in_ + r * hn);
            float hv = (1.0f - zz) * n + zz * g_h0[i];
            g_h0[i] = hv;
            bsplit(hv, g_a0h[i], g_a0l[i]);
        }
        grid_bar();

        // C: layer-1 dual (128 units NF6)
        for (int u = blockIdx.x; u < 128; u += nb) {
            int q = u & 63, mt = q & 3, nt = q >> 2;
            if (u < 64)
                mma_unit<6>(mk_mu(
                    g_a0h + (size_t)(mt * 128) * H, g_a0l + (size_t)(mt * 128) * H, H,
                    g_wih1h + (size_t)(nt * 192) * H, g_wih1l + (size_t)(nt * 192) * H, H,
                    bih1 + nt * 192, nullptr, 0,
                    g_gi + (size_t)(mt * 128) * H3 + nt * 192, H3, 32, 128, 192), smb);
            else
                mma_unit<6>(mk_mu(
                    g_a1h + (size_t)(mt * 128) * H, g_a1l + (size_t)(mt * 128) * H, H,
                    g_whh1h + (size_t)(nt * 192) * H, g_whh1l + (size_t)(nt * 192) * H, H,
                    bhh1 + nt * 192, nullptr, 0,
                    g_gh + (size_t)(mt * 128) * H3 + nt * 192, H3, 32, 128, 192), smb);
        }
        grid_bar();

        // D: layer-1 elementwise + split
        for (int i = gid; i < B * H; i += gstride) {
            int b = i >> 10, jx = i & 1023;
            size_t b3 = (size_t)b * H3;
            float r = sigm(g_gi[b3 + jx] + g_gh[b3 + jx]);
            float zz = sigm(g_gi[b3 + H + jx] + g_gh[b3 + H + jx]);
            float n = tanhf(g_gi[b3 + 2 * H + jx] + r * g_gh[b3 + 2 * H + jx]);
            float hv = (1.0f - zz) * n + zz * g_h1[i];
            g_h1[i] = hv;
            bsplit(hv, g_a1h[i], g_a1l[i]);
        }
        grid_bar();

        // E: layer-2 dual (128 units NF6)
        for (int u = blockIdx.x; u < 128; u += nb) {
            int q = u & 63, mt = q & 3, nt = q >> 2;
            if (u < 64)
                mma_unit<6>(mk_mu(
                    g_a1h + (size_t)(mt * 128) * H, g_a1l + (size_t)(mt * 128) * H, H,
                    g_wih2h + (size_t)(nt * 192) * H, g_wih2l + (size_t)(nt * 192) * H, H,
                    bih2 + nt * 192, nullptr, 0,
                    g_gi + (size_t)(mt * 128) * H3 + nt * 192, H3, 32, 128, 192), smb);
            else
                mma_unit<6>(mk_mu(
                    g_a2h + (size_t)(mt * 128) * H, g_a2l + (size_t)(mt * 128) * H, H,
                    g_whh2h + (size_t)(nt * 192) * H, g_whh2l + (size_t)(nt * 192) * H, H,
                    bhh2 + nt * 192, nullptr, 0,
                    g_gh + (size_t)(mt * 128) * H3 + nt * 192, H3, 32, 128, 192), smb);
        }
        grid_bar();

        // F: layer-2 elementwise + split
        for (int i = gid; i < B * H; i += gstride) {
            int b = i >> 10, jx = i & 1023;
            size_t b3 = (size_t)b * H3;
            float r = sigm(g_gi[b3 + jx] + g_gh[b3 + jx]);
            float zz = sigm(g_gi[b3 + H + jx] + g_gh[b3 + H + jx]);
            float n = tanhf(g_gi[b3 + 2 * H + jx] + r * g_gh[b3 + 2 * H + jx]);
            float hv = (1.0f - zz) * n + zz * g_h2[i];
            g_h2[i] = hv;
            bsplit(hv, g_a2h[i], g_a2l[i]);
        }
        grid_bar();
    }

    // ---- final logits (t = S-1) ----
    for (int u = blockIdx.x; u < 4; u += nb) {
        int mt = u;
        mma_unit<4>(mk_mu(
            g_a2h + (size_t)(mt * 128) * H, g_a2l + (size_t)(mt * 128) * H, H,
            g_owh, g_owl, H,
            nullptr, g_logc + (size_t)(mt * 128) * V, V,
            out + (size_t)(mt * 128) * (S * V) + (size_t)(S - 1) * V,
            S * V, 32, 128, V), smb);
    }
}

// ---------------- host ----------------
extern "C" void kernel_launch(void* const* d_in, const int* in_sizes, int n_in,
                              void* d_out, int out_size)
{
    (void)in_sizes; (void)n_in; (void)out_size;

    const int*   inputs = (const int*)  d_in[0];
    const float* z      = (const float*)d_in[1];
    const float* cond   = (const float*)d_in[2];
    const float* emb    = (const float*)d_in[4];
    const float* i2h_w  = (const float*)d_in[5];
    const float* i2h_b  = (const float*)d_in[6];
    const float* out_w  = (const float*)d_in[7];
    const float* out_b  = (const float*)d_in[8];
    const float* wih0 = (const float*)d_in[9];
    const float* whh0 = (const float*)d_in[10];
    const float* bih0 = (const float*)d_in[11];
    const float* bhh0 = (const float*)d_in[12];
    const float* wih1 = (const float*)d_in[13];
    const float* whh1 = (const float*)d_in[14];
    const float* bih1 = (const float*)d_in[15];
    const float* bhh1 = (const float*)d_in[16];
    const float* wih2 = (const float*)d_in[17];
    const float* whh2 = (const float*)d_in[18];
    const float* bih2 = (const float*)d_in[19];
    const float* bhh2 = (const float*)d_in[20];
    float* out = (float*)d_out;

    cudaFuncSetAttribute(decoder_k, cudaFuncAttributeMaxDynamicSharedMemorySize,
                         SMEM_TOTAL);

    int dev = 0;
    cudaGetDevice(&dev);
    int sms = 148;
    cudaDeviceGetAttribute(&sms, cudaDevAttrMultiProcessorCount, dev);
    int bpm = 1;
    cudaOccupancyMaxActiveBlocksPerMultiprocessor(&bpm, decoder_k, NTH, SMEM_TOTAL);
    if (bpm < 1) bpm = 1;

    decoder_k<<<sms * bpm, NTH, SMEM_TOTAL>>>(
        inputs, z, cond, emb, i2h_w, i2h_b, out_w, out_b,
        wih0, whh0, bih0, bhh0, wih1, whh1, bih1, bhh1,
        wih2, whh2, bih2, bhh2, out);
}

// round 8
// speedup vs baseline: 1.9808x; 1.0163x over previous
#include <cuda_runtime.h>
#include <cuda_bf16.h>
#include <cstdint>
#include <math.h>

#define B      512
#define S      200
#define H      1024
#define V      100
#define EMB    512
#define INSZ   1024
#define H3     3072
#define START_TOK 1
#define NTH    512

// smem (bytes): rows padded to 40 bf16 (80B) for conflict-free LDS
#define OFF_AXH 0u
#define OFF_AXL 10240u
#define OFF_AHH 20480u
#define OFF_AHL 30720u
#define OFF_WH  40960u
#define OFF_WL  56320u
#define BUFSTRIDE 71680u
#define SMEM_TOTAL 143360

// ---------------- fp32 scratch ----------------
__device__ float g_h0[B * H];
__device__ float g_h1[B * H];
__device__ float g_h2[B * H];
__device__ float g_gi0c[B * H3];
__device__ float g_tokt[V * H3];
__device__ float g_logc[B * V];
__device__ float g_bc0[3072];
__device__ float g_bc1[6144];
__device__ float g_bc2[6144];
__device__ unsigned g_bar_count;
__device__ unsigned g_bar_phase;

// ---------------- bf16 splits ----------------
// gate-interleaved recurrent weights
__device__ __align__(16) __nv_bfloat16 g_wc0h[3072 * H], g_wc0l[3072 * H];
__device__ __align__(16) __nv_bfloat16 g_wc1h[6144 * H], g_wc1l[6144 * H];
__device__ __align__(16) __nv_bfloat16 g_wc2h[6144 * H], g_wc2l[6144 * H];
// prologue / logits operands
__device__ __align__(16) __nv_bfloat16 g_owh[128 * H],  g_owl[128 * H];
__device__ __align__(16) __nv_bfloat16 g_ow2h[128 * H], g_ow2l[128 * H];
__device__ __align__(16) __nv_bfloat16 g_i2hh[H * INSZ], g_i2hl[H * INSZ];
__device__ __align__(16) __nv_bfloat16 g_w0ah[H3 * EMB], g_w0al[H3 * EMB];
__device__ __align__(16) __nv_bfloat16 g_w0bh[H3 * H],   g_w0bl[H3 * H];
__device__ __align__(16) __nv_bfloat16 g_embh[128 * EMB], g_embl[128 * EMB];
__device__ __align__(16) __nv_bfloat16 g_dech[B * INSZ], g_decl[B * INSZ];
// ping-pong h splits
__device__ __align__(16) __nv_bfloat16 g_a0h[2][B * H], g_a0l[2][B * H];
__device__ __align__(16) __nv_bfloat16 g_a1h[2][B * H], g_a1l[2][B * H];
__device__ __align__(16) __nv_bfloat16 g_a2h[2][B * H], g_a2l[2][B * H];

// ---------------- grid barrier ----------------
__device__ __forceinline__ void grid_bar()
{
    __syncthreads();
    if (threadIdx.x == 0) {
        __threadfence();
        volatile unsigned* php = &g_bar_phase;
        unsigned ph = *php;
        if (atomicAdd(&g_bar_count, 1u) == gridDim.x - 1u) {
            g_bar_count = 0u;
            __threadfence();
            atomicAdd(&g_bar_phase, 1u);
        } else {
            while (*php == ph) { __nanosleep(32); }
        }
        __threadfence();
    }
    __syncthreads();
}

// ---------------- helpers ----------------
__device__ __forceinline__ float sigm(float x) { return 1.0f / (1.0f + __expf(-x)); }

__device__ __forceinline__ void bsplit(float x, __nv_bfloat16& hi, __nv_bfloat16& lo)
{
    hi = __float2bfloat16(x);
    lo = __float2bfloat16(x - __bfloat162float(hi));
}

__device__ __forceinline__ uint32_t lds32(uint32_t a)
{
    uint32_t v;
    asm volatile("ld.shared.b32 %0, [%1];" : "=r"(v) : "r"(a));
    return v;
}
__device__ __forceinline__ void sts128(uint32_t a, uint4 v)
{
    asm volatile("st.shared.v4.b32 [%0], {%1,%2,%3,%4};"
                 :: "r"(a), "r"(v.x), "r"(v.y), "r"(v.z), "r"(v.w) : "memory");
}
__device__ __forceinline__ void mma16816(float* d, const uint32_t* a, const uint32_t* b)
{
    asm volatile(
        "mma.sync.aligned.m16n8k16.row.col.f32.bf16.bf16.f32 "
        "{%0,%1,%2,%3}, {%4,%5,%6,%7}, {%8,%9}, {%0,%1,%2,%3};"
        : "+f"(d[0]), "+f"(d[1]), "+f"(d[2]), "+f"(d[3])
        : "r"(a[0]), "r"(a[1]), "r"(a[2]), "r"(a[3]), "r"(b[0]), "r"(b[1]));
}

#define LDA4(dst, base, off) do { \
    (dst)[0] = lds32((base) + (off)); \
    (dst)[1] = lds32((base) + (off) + 640); \
    (dst)[2] = lds32((base) + (off) + 16); \
    (dst)[3] = lds32((base) + (off) + 656); \
} while (0)

// ---------------- generic plain GEMM unit (prologue + logits) ----------------
struct MU {
    const __nv_bfloat16 *ah, *al, *wh, *wl;
    const float *bias, *cadd;
    float* C;
    int lda, ldw, ldadd, ldc, nch, mrows, ncols;
};

__device__ __forceinline__ MU mk_mu(
    const __nv_bfloat16* ah, const __nv_bfloat16* al, int lda,
    const __nv_bfloat16* wh, const __nv_bfloat16* wl, int ldw,
    const float* bias, const float* cadd, int ldadd,
    float* C, int ldc, int nch, int mrows, int ncols)
{
    MU u;
    u.ah = ah; u.al = al; u.wh = wh; u.wl = wl;
    u.bias = bias; u.cadd = cadd; u.C = C;
    u.lda = lda; u.ldw = ldw; u.ldadd = ldadd; u.ldc = ldc;
    u.nch = nch; u.mrows = mrows; u.ncols = ncols;
    return u;
}

template<int NF>
__device__ __noinline__ void mma_unit(const MU u, uint32_t smb)
{
    const int tid  = threadIdx.x;
    const int lane = tid & 31;
    const int w    = tid >> 5;
    const int wm   = w >> 2, wn = w & 3;
    const int gq   = lane >> 2, tq = lane & 3;

    float acc[2][NF][4];
#pragma unroll
    for (int i = 0; i < 2; i++)
#pragma unroll
        for (int j = 0; j < NF; j++)
#pragma unroll
            for (int k = 0; k < 4; k++) acc[i][j][k] = 0.0f;

    const int ar = tid >> 2, aq = tid & 3;
    const bool w2 = (NF == 6) && (tid < 256);
    uint4 aR[2], wR0[2], wR1[2];

#define G_LOADG(c) do { \
    { const size_t go = (size_t)ar * u.lda + (size_t)(c) * 32 + aq * 8; \
      aR[0] = *reinterpret_cast<const uint4*>(u.ah + go); \
      aR[1] = *reinterpret_cast<const uint4*>(u.al + go); } \
    { const size_t go = (size_t)ar * u.ldw + (size_t)(c) * 32 + aq * 8; \
      wR0[0] = *reinterpret_cast<const uint4*>(u.wh + go); \
      wR0[1] = *reinterpret_cast<const uint4*>(u.wl + go); } \
    if (w2) { int idx = tid + 512; int r = idx >> 2, q = idx & 3; \
      const size_t go = (size_t)r * u.ldw + (size_t)(c) * 32 + q * 8; \
      wR1[0] = *reinterpret_cast<const uint4*>(u.wh + go); \
      wR1[1] = *reinterpret_cast<const uint4*>(u.wl + go); } \
} while (0)

#define G_STSALL(buf) do { \
    const uint32_t bb = smb + (buf) * BUFSTRIDE; \
    { uint32_t off = (uint32_t)(ar * 80 + aq * 16); \
      sts128(bb + OFF_AXH + off, aR[0]); \
      sts128(bb + OFF_AXL + off, aR[1]); \
      sts128(bb + OFF_WH + off, wR0[0]); \
      sts128(bb + OFF_WL + off, wR0[1]); } \
    if (w2) { int idx = tid + 512; int r = idx >> 2, q = idx & 3; \
      uint32_t off = (uint32_t)(r * 80 + q * 16); \
      sts128(bb + OFF_WH + off, wR1[0]); \
      sts128(bb + OFF_WL + off, wR1[1]); } \
} while (0)

    G_LOADG(0);
    G_STSALL(0);
    __syncthreads();
    for (int c = 0; c < u.nch; c++) {
        if (c + 1 < u.nch) G_LOADG(c + 1);
        const uint32_t bb = smb + (uint32_t)(c & 1) * BUFSTRIDE;
#pragma unroll
        for (int ks = 0; ks < 2; ks++) {
            const int kb = ks * 16;
            uint32_t bh[NF][2], bl[NF][2];
#pragma unroll
            for (int nf = 0; nf < NF; nf++) {
                int n = wn * (NF * 8) + nf * 8 + gq;
                uint32_t off = (uint32_t)(n * 80 + (kb + 2 * tq) * 2);
                bh[nf][0] = lds32(bb + OFF_WH + off);
                bh[nf][1] = lds32(bb + OFF_WH + off + 16);
                bl[nf][0] = lds32(bb + OFF_WL + off);
                bl[nf][1] = lds32(bb + OFF_WL + off + 16);
            }
#pragma unroll
            for (int mf = 0; mf < 2; mf++) {
                int r = wm * 32 + mf * 16 + gq;
                uint32_t off = (uint32_t)(r * 80 + (kb + 2 * tq) * 2);
                uint32_t ah[4], al[4];
                LDA4(ah, bb + OFF_AXH, off);
                LDA4(al, bb + OFF_AXL, off);
#pragma unroll
                for (int nf = 0; nf < NF; nf++) {
                    mma16816(acc[mf][nf], ah, bh[nf]);
                    mma16816(acc[mf][nf], ah, bl[nf]);
                    mma16816(acc[mf][nf], al, bh[nf]);
                }
            }
        }
        if (c + 1 < u.nch) G_STSALL((c + 1) & 1);
        __syncthreads();
    }
#undef G_LOADG
#undef G_STSALL

#pragma unroll
    for (int mf = 0; mf < 2; mf++) {
#pragma unroll
        for (int half = 0; half < 2; half++) {
            int m = wm * 32 + mf * 16 + gq + half * 8;
            if (m >= u.mrows) continue;
            float* crow = u.C + (size_t)m * u.ldc;
            const float* car = u.cadd ? u.cadd + (size_t)m * u.ldadd : nullptr;
#pragma unroll
            for (int nf = 0; nf < NF; nf++) {
#pragma unroll
                for (int e = 0; e < 2; e++) {
                    int col = wn * (NF * 8) + nf * 8 + 2 * tq + e;
                    if (col < u.ncols) {
                        float v = acc[mf][nf][half * 2 + e];
                        if (u.bias) v += u.bias[col];
                        if (car) v += car[col];
                        crow[col] = v;
                    }
                }
            }
        }
    }
    __syncthreads();
}

// ---------------- fused layer-1/2 unit: GEMM + GRU epilogue ----------------
// unit = 128 m-rows x 32 j-cols; W block = 192 rows (4 octets x 6 gates x 8)
struct FU {
    const __nv_bfloat16 *xh, *xl, *hh, *hl;   // [B,H] splits
    const __nv_bfloat16 *wh, *wl;             // Wcat block [192,1024]
    const float* bc;                           // bias block [192]
    float* hfp;                                // g_h{l}
    __nv_bfloat16 *oah, *oal;                  // out splits (nxt)
    int m0, j0;
};

__device__ __noinline__ void fused_l12(const FU u, uint32_t smb)
{
    const int tid  = threadIdx.x;
    const int lane = tid & 31;
    const int w    = tid >> 5;
    const int wm   = w >> 2, wn = w & 3;      // 4m x 4n; wn = j-octet
    const int gq   = lane >> 2, tq = lane & 3;

    float acc[2][6][4];
#pragma unroll
    for (int i = 0; i < 2; i++)
#pragma unroll
        for (int j = 0; j < 6; j++)
#pragma unroll
            for (int k = 0; k < 4; k++) acc[i][j][k] = 0.0f;

    const int ar = tid >> 2, aq = tid & 3;            // A: 128 rows, 1 uint4 ea
    const int w2r = (512 + (tid & 255)) >> 2, w2q = (512 + (tid & 255)) & 3;
    const bool w2hi = (tid < 256);
    uint4 xR[2], hR[2], wR0[2], wR1;

#define F_LOADG(c) do { \
    { const size_t go = (size_t)(u.m0 + ar) * H + (size_t)(c) * 32 + aq * 8; \
      xR[0] = *reinterpret_cast<const uint4*>(u.xh + go); \
      xR[1] = *reinterpret_cast<const uint4*>(u.xl + go); \
      hR[0] = *reinterpret_cast<const uint4*>(u.hh + go); \
      hR[1] = *reinterpret_cast<const uint4*>(u.hl + go); } \
    { const size_t go = (size_t)ar * H + (size_t)(c) * 32 + aq * 8; \
      wR0[0] = *reinterpret_cast<const uint4*>(u.wh + go); \
      wR0[1] = *reinterpret_cast<const uint4*>(u.wl + go); } \
    { const size_t go = (size_t)w2r * H + (size_t)(c) * 32 + w2q * 8; \
      wR1 = *reinterpret_cast<const uint4*>((w2hi ? u.wh : u.wl) + go); } \
} while (0)

#define F_STSALL(buf) do { \
    const uint32_t bb = smb + (buf) * BUFSTRIDE; \
    uint32_t off = (uint32_t)(ar * 80 + aq * 16); \
    sts128(bb + OFF_AXH + off, xR[0]); \
    sts128(bb + OFF_AXL + off, xR[1]); \
    sts128(bb + OFF_AHH + off, hR[0]); \
    sts128(bb + OFF_AHL + off, hR[1]); \
    sts128(bb + OFF_WH + off, wR0[0]); \
    sts128(bb + OFF_WL + off, wR0[1]); \
    uint32_t off2 = (uint32_t)(w2r * 80 + w2q * 16); \
    sts128(bb + (w2hi ? OFF_WH : OFF_WL) + off2, wR1); \
} while (0)

    F_LOADG(0);
    F_STSALL(0);
    __syncthreads();
    for (int c = 0; c < 32; c++) {
        if (c + 1 < 32) F_LOADG(c + 1);
        const uint32_t bb = smb + (uint32_t)(c & 1) * BUFSTRIDE;
#pragma unroll
        for (int ks = 0; ks < 2; ks++) {
            const int kb = ks * 16;
            uint32_t bh[6][2], bl[6][2];
#pragma unroll
            for (int nf = 0; nf < 6; nf++) {
                int n = wn * 48 + nf * 8 + gq;
                uint32_t off = (uint32_t)(n * 80 + (kb + 2 * tq) * 2);
                bh[nf][0] = lds32(bb + OFF_WH + off);
                bh[nf][1] = lds32(bb + OFF_WH + off + 16);
                bl[nf][0] = lds32(bb + OFF_WL + off);
                bl[nf][1] = lds32(bb + OFF_WL + off + 16);
            }
#pragma unroll
            for (int mf = 0; mf < 2; mf++) {
                int r = wm * 32 + mf * 16 + gq;
                uint32_t off = (uint32_t)(r * 80 + (kb + 2 * tq) * 2);
                uint32_t fh[4], fl[4];
                LDA4(fh, bb + OFF_AXH, off);
                LDA4(fl, bb + OFF_AXL, off);
#pragma unroll
                for (int nf = 0; nf < 3; nf++) {
                    mma16816(acc[mf][nf], fh, bh[nf]);
                    mma16816(acc[mf][nf], fh, bl[nf]);
                    mma16816(acc[mf][nf], fl, bh[nf]);
                }
                LDA4(fh, bb + OFF_AHH, off);
                LDA4(fl, bb + OFF_AHL, off);
#pragma unroll
                for (int nf = 3; nf < 6; nf++) {
                    mma16816(acc[mf][nf], fh, bh[nf]);
                    mma16816(acc[mf][nf], fh, bl[nf]);
                    mma16816(acc[mf][nf], fl, bh[nf]);
                }
            }
        }
        if (c + 1 < 32) F_STSALL((c + 1) & 1);
        __syncthreads();
    }
#undef F_LOADG
#undef F_STSALL

    // fused GRU epilogue
#pragma unroll
    for (int e = 0; e < 2; e++) {
        const int j = u.j0 + wn * 8 + 2 * tq + e;
        const float* bcb = u.bc + wn * 48 + 2 * tq + e;
        float b0 = bcb[0], b1 = bcb[8], b2 = bcb[16];
        float b3 = bcb[24], b4 = bcb[32], b5 = bcb[40];
#pragma unroll
        for (int mf = 0; mf < 2; mf++) {
#pragma unroll
            for (int half = 0; half < 2; half++) {
                int m = u.m0 + wm * 32 + mf * 16 + gq + half * 8;
                int ai = half * 2 + e;
                float ir = acc[mf][0][ai] + b0;
                float iz = acc[mf][1][ai] + b1;
                float in_ = acc[mf][2][ai] + b2;
                float hr = acc[mf][3][ai] + b3;
                float hz = acc[mf][4][ai] + b4;
                float hn = acc[mf][5][ai] + b5;
                float r = sigm(ir + hr), zz = sigm(iz + hz);
                float n = tanhf(in_ + r * hn);
                size_t idx = (size_t)m * H + j;
                float hv = (1.0f - zz) * n + zz * u.hfp[idx];
                u.hfp[idx] = hv;
                bsplit(hv, u.oah[idx], u.oal[idx]);
            }
        }
    }
    __syncthreads();
}

// ---------------- fused layer-0 unit ----------------
// unit = 64 m-rows x 64 j; W block = 192 rows (8 octets x 3 gates x 8)
struct F0 {
    const __nv_bfloat16 *hh, *hl;
    const __nv_bfloat16 *wh, *wl;
    const float* bc;
    const int* inp;
    int t, m0, j0;
    float* hfp;
    __nv_bfloat16 *oah, *oal;
};

__device__ __noinline__ void fused_l0(const F0 u, uint32_t smb)
{
    const int tid  = threadIdx.x;
    const int lane = tid & 31;
    const int w    = tid >> 5;
    const int wm   = w >> 3, wn = w & 7;     // 2m x 8n; wn = j-octet
    const int gq   = lane >> 2, tq = lane & 3;

    float acc[2][3][4];
#pragma unroll
    for (int i = 0; i < 2; i++)
#pragma unroll
        for (int j = 0; j < 3; j++)
#pragma unroll
            for (int k = 0; k < 4; k++) acc[i][j][k] = 0.0f;

    const int ar = tid >> 2, aq = tid & 3;   // A: rows 0..63 use tid<256
    const bool aload = (tid < 256);
    const int w2r = (512 + (tid & 255)) >> 2, w2q = (512 + (tid & 255)) & 3;
    const bool w2hi = (tid < 256);
    uint4 hR[2], wR0[2], wR1;

#define Z_LOADG(c) do { \
    if (aload) { const size_t go = (size_t)(u.m0 + ar) * H + (size_t)(c) * 32 + aq * 8; \
      hR[0] = *reinterpret_cast<const uint4*>(u.hh + go); \
      hR[1] = *reinterpret_cast<const uint4*>(u.hl + go); } \
    { const size_t go = (size_t)ar * H + (size_t)(c) * 32 + aq * 8; \
      wR0[0] = *reinterpret_cast<const uint4*>(u.wh + go); \
      wR0[1] = *reinterpret_cast<const uint4*>(u.wl + go); } \
    { const size_t go = (size_t)w2r * H + (size_t)(c) * 32 + w2q * 8; \
      wR1 = *reinterpret_cast<const uint4*>((w2hi ? u.wh : u.wl) + go); } \
} while (0)

#define Z_STSALL(buf) do { \
    const uint32_t bb = smb + (buf) * BUFSTRIDE; \
    uint32_t off = (uint32_t)(ar * 80 + aq * 16); \
    if (aload) { sts128(bb + OFF_AXH + off, hR[0]); \
                 sts128(bb + OFF_AXL + off, hR[1]); } \
    sts128(bb + OFF_WH + off, wR0[0]); \
    sts128(bb + OFF_WL + off, wR0[1]); \
    uint32_t off2 = (uint32_t)(w2r * 80 + w2q * 16); \
    sts128(bb + (w2hi ? OFF_WH : OFF_WL) + off2, wR1); \
} while (0)

    Z_LOADG(0);
    Z_STSALL(0);
    __syncthreads();
    for (int c = 0; c < 32; c++) {
        if (c + 1 < 32) Z_LOADG(c + 1);
        const uint32_t bb = smb + (uint32_t)(c & 1) * BUFSTRIDE;
#pragma unroll
        for (int ks = 0; ks < 2; ks++) {
            const int kb = ks * 16;
            uint32_t bh[3][2], bl[3][2];
#pragma unroll
            for (int nf = 0; nf < 3; nf++) {
                int n = wn * 24 + nf * 8 + gq;
                uint32_t off = (uint32_t)(n * 80 + (kb + 2 * tq) * 2);
                bh[nf][0] = lds32(bb + OFF_WH + off);
                bh[nf][1] = lds32(bb + OFF_WH + off + 16);
                bl[nf][0] = lds32(bb + OFF_WL + off);
                bl[nf][1] = lds32(bb + OFF_WL + off + 16);
            }
#pragma unroll
            for (int mf = 0; mf < 2; mf++) {
                int r = wm * 32 + mf * 16 + gq;
                uint32_t off = (uint32_t)(r * 80 + (kb + 2 * tq) * 2);
                uint32_t fh[4], fl[4];
                LDA4(fh, bb + OFF_AXH, off);
                LDA4(fl, bb + OFF_AXL, off);
#pragma unroll
                for (int nf = 0; nf < 3; nf++) {
                    mma16816(acc[mf][nf], fh, bh[nf]);
                    mma16816(acc[mf][nf], fh, bl[nf]);
                    mma16816(acc[mf][nf], fl, bh[nf]);
                }
            }
        }
        if (c + 1 < 32) Z_STSALL((c + 1) & 1);
        __syncthreads();
    }
#undef Z_LOADG
#undef Z_STSALL

#pragma unroll
    for (int e = 0; e < 2; e++) {
        const int j = u.j0 + wn * 8 + 2 * tq + e;
        const float* bcb = u.bc + wn * 24 + 2 * tq + e;
        float b0 = bcb[0], b1 = bcb[8], b2 = bcb[16];
#pragma unroll
        for (int mf = 0; mf < 2; mf++) {
#pragma unroll
            for (int half = 0; half < 2; half++) {
                int m = u.m0 + wm * 32 + mf * 16 + gq + half * 8;
                int ai = half * 2 + e;
                int tok = (u.t == 0) ? START_TOK : u.inp[m * S + u.t - 1];
                const float* tr = g_tokt + (size_t)tok * H3 + j;
                const float* gc = g_gi0c + (size_t)m * H3 + j;
                float ir = tr[0] + gc[0];
                float iz = tr[H] + gc[H];
                float in_ = tr[2 * H] + gc[2 * H];
                float hr = acc[mf][0][ai] + b0;
                float hz = acc[mf][1][ai] + b1;
                float hn = acc[mf][2][ai] + b2;
                float r = sigm(ir + hr), zz = sigm(iz + hz);
                float n = tanhf(in_ + r * hn);
                size_t idx = (size_t)m * H + j;
                float hv = (1.0f - zz) * n + zz * u.hfp[idx];
                u.hfp[idx] = hv;
                bsplit(hv, u.oah[idx], u.oal[idx]);
            }
        }
    }
    __syncthreads();
}

// ---------------- persistent kernel ----------------
__global__ __launch_bounds__(NTH, 1) void decoder_k(
    const int* __restrict__ inputs, const float* __restrict__ z,
    const float* __restrict__ cond, const float* __restrict__ emb,
    const float* __restrict__ i2h_w, const float* __restrict__ i2h_b,
    const float* __restrict__ out_w, const float* __restrict__ out_b,
    const float* __restrict__ wih0, const float* __restrict__ whh0,
    const float* __restrict__ bih0, const float* __restrict__ bhh0,
    const float* __restrict__ wih1, const float* __restrict__ whh1,
    const float* __restrict__ bih1, const float* __restrict__ bhh1,
    const float* __restrict__ wih2, const float* __restrict__ whh2,
    const float* __restrict__ bih2, const float* __restrict__ bhh2,
    float* __restrict__ out)
{
    extern __shared__ __align__(16) char smem[];
    uint32_t smb;
    asm("{ .reg .u64 t; cvta.to.shared.u64 t, %1; cvt.u32.u64 %0, t; }"
        : "=r"(smb) : "l"(smem));

    const int tid = threadIdx.x;
    const unsigned nb = gridDim.x;
    const int gid = blockIdx.x * NTH + tid;
    const int gstride = nb * NTH;

    // ---- P0: splits + gate-interleaved weight layouts ----
    // wc0: layer0 whh, [16 jb][8 jo][3 g][8 jr]
    for (int i = gid; i < 3072 * 1024; i += gstride) {
        int rd = i >> 10, k = i & 1023;
        int jb = rd / 192, r2 = rd - jb * 192;
        int jo = r2 / 24, r3 = r2 - jo * 24;
        int g = r3 >> 3, jr = r3 & 7;
        int j = jb * 64 + jo * 8 + jr;
        bsplit(whh0[(size_t)(g * H + j) * H + k], g_wc0h[i], g_wc0l[i]);
    }
    // wc1/wc2: [32 jb][4 jo][6 g][8 jr]
    {
        const float* wi[2] = {wih1, wih2};
        const float* wr[2] = {whh1, whh2};
        __nv_bfloat16* dh[2] = {g_wc1h, g_wc2h};
        __nv_bfloat16* dl[2] = {g_wc1l, g_wc2l};
        for (int l = 0; l < 2; l++)
            for (int i = gid; i < 6144 * 1024; i += gstride) {
                int rd = i >> 10, k = i & 1023;
                int jb = rd / 192, r2 = rd - jb * 192;
                int jo = r2 / 48, r3 = r2 - jo * 48;
                int g = r3 >> 3, jr = r3 & 7;
                int j = jb * 32 + jo * 8 + jr;
                float v = (g < 3) ? wi[l][(size_t)(g * H + j) * H + k]
                                  : wr[l][(size_t)((g - 3) * H + j) * H + k];
                bsplit(v, dh[l][i], dl[l][i]);
            }
    }
    // bias cats
    for (int i = gid; i < 3072; i += gstride) {
        int jb = i / 192, r2 = i - jb * 192;
        int jo = r2 / 24, r3 = r2 - jo * 24;
        int g = r3 >> 3, jr = r3 & 7;
        g_bc0[i] = bhh0[g * H + jb * 64 + jo * 8 + jr];
    }
    {
        const float* bi[2] = {bih1, bih2};
        const float* br[2] = {bhh1, bhh2};
        float* bd[2] = {g_bc1, g_bc2};
        for (int l = 0; l < 2; l++)
            for (int i = gid; i < 6144; i += gstride) {
                int jb = i / 192, r2 = i - jb * 192;
                int jo = r2 / 48, r3 = r2 - jo * 48;
                int g = r3 >> 3, jr = r3 & 7;
                int j = jb * 32 + jo * 8 + jr;
                bd[l][i] = (g < 3) ? bi[l][g * H + j] : br[l][(g - 3) * H + j];
            }
    }
    for (int i = gid; i < H * INSZ; i += gstride) bsplit(i2h_w[i], g_i2hh[i], g_i2hl[i]);
    for (int i = gid; i < H3 * EMB; i += gstride) {
        int r = i >> 9, c = i & 511;
        bsplit(wih0[(size_t)r * (EMB + INSZ) + c], g_w0ah[i], g_w0al[i]);
    }
    for (int i = gid; i < H3 * H; i += gstride) {
        int r = i >> 10, c = i & 1023;
        bsplit(wih0[(size_t)r * (EMB + INSZ) + EMB + c], g_w0bh[i], g_w0bl[i]);
    }
    for (int i = gid; i < 128 * EMB; i += gstride) {
        int r = i >> 9, c = i & 511;
        bsplit(r < V ? emb[r * EMB + c] : 0.0f, g_embh[i], g_embl[i]);
    }
    for (int i = gid; i < 128 * H; i += gstride) {
        int r = i >> 10, c = i & 1023;
        bsplit(r < V ? out_w[(size_t)r * (H + INSZ) + c] : 0.0f, g_owh[i], g_owl[i]);
        bsplit(r < V ? out_w[(size_t)r * (H + INSZ) + H + c] : 0.0f, g_ow2h[i], g_ow2l[i]);
    }
    for (int i = gid; i < B * INSZ; i += gstride) {
        int b = i >> 10, jx = i & 1023;
        float v = (jx < 512) ? z[b * 512 + jx] : cond[b * 512 + jx - 512];
        bsplit(v, g_dech[i], g_decl[i]);
    }
    grid_bar();

    // ---- P2: prologue GEMMs (116 units) ----
    for (int u = blockIdx.x; u < 116; u += nb) {
        if (u < 32) {
            int mt = u & 3, nt = u >> 2;
            mma_unit<4>(mk_mu(
                g_dech + (size_t)(mt * 128) * INSZ, g_decl + (size_t)(mt * 128) * INSZ, INSZ,
                g_i2hh + (size_t)(nt * 128) * INSZ, g_i2hl + (size_t)(nt * 128) * INSZ, INSZ,
                i2h_b + nt * 128, nullptr, 0,
                g_h0 + (size_t)(mt * 128) * H + nt * 128, H, 32, 128, 128), smb);
        } else if (u < 96) {
            int q = u - 32, mt = q & 3, nt = q >> 2;
            mma_unit<6>(mk_mu(
                g_dech + (size_t)(mt * 128) * INSZ, g_decl + (size_t)(mt * 128) * INSZ, INSZ,
                g_w0bh + (size_t)(nt * 192) * H, g_w0bl + (size_t)(nt * 192) * H, H,
                bih0 + nt * 192, nullptr, 0,
                g_gi0c + (size_t)(mt * 128) * H3 + nt * 192, H3, 32, 128, 192), smb);
        } else if (u < 112) {
            int nt = u - 96;
            mma_unit<6>(mk_mu(
                g_embh, g_embl, EMB,
                g_w0ah + (size_t)(nt * 192) * EMB, g_w0al + (size_t)(nt * 192) * EMB, EMB,
                nullptr, nullptr, 0,
                g_tokt + nt * 192, H3, 16, V, 192), smb);
        } else {
            int mt = u - 112;
            mma_unit<4>(mk_mu(
                g_dech + (size_t)(mt * 128) * INSZ, g_decl + (size_t)(mt * 128) * INSZ, INSZ,
                g_ow2h, g_ow2l, H,
                out_b, nullptr, 0,
                g_logc + (size_t)(mt * 128) * V, V, 32, 128, V), smb);
        }
    }
    grid_bar();

    // ---- P3: broadcast h_init + splits into buffer 0 ----
    for (int i = gid; i < B * H; i += gstride) {
        float v = g_h0[i];
        g_h1[i] = v; g_h2[i] = v;
        __nv_bfloat16 hi, lo;
        bsplit(v, hi, lo);
        g_a0h[0][i] = hi; g_a0l[0][i] = lo;
        g_a1h[0][i] = hi; g_a1l[0][i] = lo;
        g_a2h[0][i] = hi; g_a2l[0][i] = lo;
    }
    grid_bar();

    // ---- recurrent loop: 3 barriers/step ----
    for (int t = 0; t < S; t++) {
        const int cur = t & 1, nxt = cur ^ 1;

        // Phase A: 128 fused-l0 units + 4 logits(t-1)
        {
            const int U = 128 + (t > 0 ? 4 : 0);
            for (int u = blockIdx.x; u < U; u += nb) {
                if (u < 128) {
                    int mb = u & 7, jb = u >> 3;
                    F0 f;
                    f.hh = g_a0h[cur]; f.hl = g_a0l[cur];
                    f.wh = g_wc0h + (size_t)(jb * 192) * H;
                    f.wl = g_wc0l + (size_t)(jb * 192) * H;
                    f.bc = g_bc0 + jb * 192;
                    f.inp = inputs; f.t = t;
                    f.m0 = mb * 64; f.j0 = jb * 64;
                    f.hfp = g_h0; f.oah = g_a0h[nxt]; f.oal = g_a0l[nxt];
                    fused_l0(f, smb);
                } else {
                    int mt = u - 128;
                    mma_unit<4>(mk_mu(
                        g_a2h[cur] + (size_t)(mt * 128) * H,
                        g_a2l[cur] + (size_t)(mt * 128) * H, H,
                        g_owh, g_owl, H,
                        nullptr, g_logc + (size_t)(mt * 128) * V, V,
                        out + (size_t)(mt * 128) * (S * V) + (size_t)(t - 1) * V,
                        S * V, 32, 128, V), smb);
                }
            }
        }
        grid_bar();

        // Phase C: 128 fused layer-1 units
        for (int u = blockIdx.x; u < 128; u += nb) {
            int mb = u & 3, jb = u >> 2;
            FU f;
            f.xh = g_a0h[nxt]; f.xl = g_a0l[nxt];
            f.hh = g_a1h[cur]; f.hl = g_a1l[cur];
            f.wh = g_wc1h + (size_t)(jb * 192) * H;
            f.wl = g_wc1l + (size_t)(jb * 192) * H;
            f.bc = g_bc1 + jb * 192;
            f.m0 = mb * 128; f.j0 = jb * 32;
            f.hfp = g_h1; f.oah = g_a1h[nxt]; f.oal = g_a1l[nxt];
            fused_l12(f, smb);
        }
        grid_bar();

        // Phase E: 128 fused layer-2 units
        for (int u = blockIdx.x; u < 128; u += nb) {
            int mb = u & 3, jb = u >> 2;
            FU f;
            f.xh = g_a1h[nxt]; f.xl = g_a1l[nxt];
            f.hh = g_a2h[cur]; f.hl = g_a2l[cur];
            f.wh = g_wc2h + (size_t)(jb * 192) * H;
            f.wl = g_wc2l + (size_t)(jb * 192) * H;
            f.bc = g_bc2 + jb * 192;
            f.m0 = mb * 128; f.j0 = jb * 32;
            f.hfp = g_h2; f.oah = g_a2h[nxt]; f.oal = g_a2l[nxt];
            fused_l12(f, smb);
        }
        grid_bar();
    }

    // ---- final logits (state after step S-1 lives in buffer S&1 = 0) ----
    for (int u = blockIdx.x; u < 4; u += nb) {
        int mt = u;
        mma_unit<4>(mk_mu(
            g_a2h[S & 1] + (size_t)(mt * 128) * H,
            g_a2l[S & 1] + (size_t)(mt * 128) * H, H,
            g_owh, g_owl, H,
            nullptr, g_logc + (size_t)(mt * 128) * V, V,
            out + (size_t)(mt * 128) * (S * V) + (size_t)(S - 1) * V,
            S * V, 32, 128, V), smb);
    }
}

// ---------------- host ----------------
extern "C" void kernel_launch(void* const* d_in, const int* in_sizes, int n_in,
                              void* d_out, int out_size)
{
    (void)in_sizes; (void)n_in; (void)out_size;

    const int*   inputs = (const int*)  d_in[0];
    const float* z      = (const float*)d_in[1];
    const float* cond   = (const float*)d_in[2];
    const float* emb    = (const float*)d_in[4];
    const float* i2h_w  = (const float*)d_in[5];
    const float* i2h_b  = (const float*)d_in[6];
    const float* out_w  = (const float*)d_in[7];
    const float* out_b  = (const float*)d_in[8];
    const float* wih0 = (const float*)d_in[9];
    const float* whh0 = (const float*)d_in[10];
    const float* bih0 = (const float*)d_in[11];
    const float* bhh0 = (const float*)d_in[12];
    const float* wih1 = (const float*)d_in[13];
    const float* whh1 = (const float*)d_in[14];
    const float* bih1 = (const float*)d_in[15];
    const float* bhh1 = (const float*)d_in[16];
    const float* wih2 = (const float*)d_in[17];
    const float* whh2 = (const float*)d_in[18];
    const float* bih2 = (const float*)d_in[19];
    const float* bhh2 = (const float*)d_in[20];
    float* out = (float*)d_out;

    cudaFuncSetAttribute(decoder_k, cudaFuncAttributeMaxDynamicSharedMemorySize,
                         SMEM_TOTAL);

    int dev = 0;
    cudaGetDevice(&dev);
    int sms = 148;
    cudaDeviceGetAttribute(&sms, cudaDevAttrMultiProcessorCount, dev);
    int bpm = 1;
    cudaOccupancyMaxActiveBlocksPerMultiprocessor(&bpm, decoder_k, NTH, SMEM_TOTAL);
    if (bpm < 1) bpm = 1;

    decoder_k<<<sms * bpm, NTH, SMEM_TOTAL>>>(
        inputs, z, cond, emb, i2h_w, i2h_b, out_w, out_b,
        wih0, whh0, bih0, bhh0, wih1, whh1, bih1, bhh1,
        wih2, whh2, bih2, bhh2, out);
}

// round 9
// speedup vs baseline: 2.3810x; 1.2020x over previous
#include <cuda_runtime.h>
#include <cuda_bf16.h>
#include <cstdint>
#include <math.h>

#define B      512
#define S      200
#define H      1024
#define V      100
#define EMB    512
#define INSZ   1024
#define H3     3072
#define START_TOK 1
#define NTH    512

// smem (bytes): rows padded to 40 bf16 (80B) for conflict-free LDS/LDSM
#define OFF_AXH 0u
#define OFF_AXL 10240u
#define OFF_AHH 20480u
#define OFF_AHL 30720u
#define OFF_WH  40960u
#define OFF_WL  56320u
#define BUFSTRIDE 71680u
#define SMEM_TOTAL 143360

// ---------------- fp32 scratch ----------------
__device__ float g_h0[B * H];
__device__ float g_h1[B * H];
__device__ float g_h2[B * H];
__device__ float g_gi0c[B * H3];
__device__ float g_tokt[V * H3];
__device__ float g_logc[B * V];
__device__ float g_bc0[3072];
__device__ float g_bc1[6144];
__device__ float g_bc2[6144];
__device__ unsigned g_bar_count;
__device__ unsigned g_bar_phase;

// ---------------- bf16 splits ----------------
__device__ __align__(16) __nv_bfloat16 g_wc0h[3072 * H], g_wc0l[3072 * H];
__device__ __align__(16) __nv_bfloat16 g_wc1h[6144 * H], g_wc1l[6144 * H];
__device__ __align__(16) __nv_bfloat16 g_wc2h[6144 * H], g_wc2l[6144 * H];
__device__ __align__(16) __nv_bfloat16 g_owh[128 * H],  g_owl[128 * H];
__device__ __align__(16) __nv_bfloat16 g_ow2h[128 * H], g_ow2l[128 * H];
__device__ __align__(16) __nv_bfloat16 g_i2hh[H * INSZ], g_i2hl[H * INSZ];
__device__ __align__(16) __nv_bfloat16 g_w0ah[H3 * EMB], g_w0al[H3 * EMB];
__device__ __align__(16) __nv_bfloat16 g_w0bh[H3 * H],   g_w0bl[H3 * H];
__device__ __align__(16) __nv_bfloat16 g_embh[128 * EMB], g_embl[128 * EMB];
__device__ __align__(16) __nv_bfloat16 g_dech[B * INSZ], g_decl[B * INSZ];
__device__ __align__(16) __nv_bfloat16 g_a0h[2][B * H], g_a0l[2][B * H];
__device__ __align__(16) __nv_bfloat16 g_a1h[2][B * H], g_a1l[2][B * H];
__device__ __align__(16) __nv_bfloat16 g_a2h[2][B * H], g_a2l[2][B * H];

// ---------------- grid barrier ----------------
__device__ __forceinline__ void grid_bar()
{
    __syncthreads();
    if (threadIdx.x == 0) {
        __threadfence();
        volatile unsigned* php = &g_bar_phase;
        unsigned ph = *php;
        if (atomicAdd(&g_bar_count, 1u) == gridDim.x - 1u) {
            g_bar_count = 0u;
            __threadfence();
            atomicAdd(&g_bar_phase, 1u);
        } else {
            while (*php == ph) { __nanosleep(32); }
        }
        __threadfence();
    }
    __syncthreads();
}

// ---------------- helpers ----------------
__device__ __forceinline__ float sigm(float x) { return 1.0f / (1.0f + __expf(-x)); }

__device__ __forceinline__ void bsplit(float x, __nv_bfloat16& hi, __nv_bfloat16& lo)
{
    hi = __float2bfloat16(x);
    lo = __float2bfloat16(x - __bfloat162float(hi));
}

__device__ __forceinline__ void mma16816(float* d, const uint32_t* a, const uint32_t* b)
{
    asm volatile(
        "mma.sync.aligned.m16n8k16.row.col.f32.bf16.bf16.f32 "
        "{%0,%1,%2,%3}, {%4,%5,%6,%7}, {%8,%9}, {%0,%1,%2,%3};"
        : "+f"(d[0]), "+f"(d[1]), "+f"(d[2]), "+f"(d[3])
        : "r"(a[0]), "r"(a[1]), "r"(a[2]), "r"(a[3]), "r"(b[0]), "r"(b[1]));
}
__device__ __forceinline__ void ldsm4(uint32_t& r0, uint32_t& r1, uint32_t& r2,
                                      uint32_t& r3, uint32_t a)
{
    asm volatile("ldmatrix.sync.aligned.m8n8.x4.shared.b16 {%0,%1,%2,%3}, [%4];"
                 : "=r"(r0), "=r"(r1), "=r"(r2), "=r"(r3) : "r"(a));
}
__device__ __forceinline__ void ldsm2(uint32_t& r0, uint32_t& r1, uint32_t a)
{
    asm volatile("ldmatrix.sync.aligned.m8n8.x2.shared.b16 {%0,%1}, [%2];"
                 : "=r"(r0), "=r"(r1) : "r"(a));
}
__device__ __forceinline__ void cpasync16(uint32_t dst, const void* src)
{
    asm volatile("cp.async.cg.shared.global [%0], [%1], 16;" :: "r"(dst), "l"(src));
}
#define CP_COMMIT() asm volatile("cp.async.commit_group;" ::: "memory")
#define CP_WAIT0()  asm volatile("cp.async.wait_group 0;" ::: "memory")

// ---------------- generic plain GEMM unit (prologue + logits) ----------------
struct MU {
    const __nv_bfloat16 *ah, *al, *wh, *wl;
    const float *bias, *cadd;
    float* C;
    int lda, ldw, ldadd, ldc, nch, mrows, ncols;
};

__device__ __forceinline__ MU mk_mu(
    const __nv_bfloat16* ah, const __nv_bfloat16* al, int lda,
    const __nv_bfloat16* wh, const __nv_bfloat16* wl, int ldw,
    const float* bias, const float* cadd, int ldadd,
    float* C, int ldc, int nch, int mrows, int ncols)
{
    MU u;
    u.ah = ah; u.al = al; u.wh = wh; u.wl = wl;
    u.bias = bias; u.cadd = cadd; u.C = C;
    u.lda = lda; u.ldw = ldw; u.ldadd = ldadd; u.ldc = ldc;
    u.nch = nch; u.mrows = mrows; u.ncols = ncols;
    return u;
}

template<int NF>
__device__ __noinline__ void mma_unit(const MU u, uint32_t smb)
{
    const int tid  = threadIdx.x;
    const int lane = tid & 31;
    const int w    = tid >> 5;
    const int wm   = w >> 2, wn = w & 3;
    const int gq   = lane >> 2, tq = lane & 3;
    constexpr int NP = NF / 2;

    float acc[2][NF][4];
#pragma unroll
    for (int i = 0; i < 2; i++)
#pragma unroll
        for (int j = 0; j < NF; j++)
#pragma unroll
            for (int k = 0; k < 4; k++) acc[i][j][k] = 0.0f;

    const int ar = tid >> 2, aq = tid & 3;
    const bool w2 = (NF == 6) && (tid < 256);
    const int w2i = 512 + tid;
    const int w2r = w2i >> 2, w2q = w2i & 3;
    const uint32_t soff  = (uint32_t)(ar * 80 + aq * 16);
    const uint32_t soff2 = (uint32_t)(w2r * 80 + w2q * 16);

    const uint32_t a_off = (uint32_t)((wm * 32 + (lane & 15)) * 80 + (lane >> 4) * 16);
    uint32_t b_off[NP];
#pragma unroll
    for (int p = 0; p < NP; p++)
        b_off[p] = (uint32_t)((wn * (NF * 8) + p * 16 + ((lane >> 4) << 3) + (lane & 7)) * 80
                              + ((lane >> 3) & 1) * 16);

#define G_ASYNC(c, buf) do { \
    const uint32_t bb = smb + (uint32_t)(buf) * BUFSTRIDE; \
    size_t goA = (size_t)ar * u.lda + (size_t)(c) * 32 + aq * 8; \
    size_t goW = (size_t)ar * u.ldw + (size_t)(c) * 32 + aq * 8; \
    cpasync16(bb + OFF_AXH + soff, u.ah + goA); \
    cpasync16(bb + OFF_AXL + soff, u.al + goA); \
    cpasync16(bb + OFF_WH + soff, u.wh + goW); \
    cpasync16(bb + OFF_WL + soff, u.wl + goW); \
    if (w2) { size_t go2 = (size_t)w2r * u.ldw + (size_t)(c) * 32 + w2q * 8; \
        cpasync16(bb + OFF_WH + soff2, u.wh + go2); \
        cpasync16(bb + OFF_WL + soff2, u.wl + go2); } \
    CP_COMMIT(); \
} while (0)

    G_ASYNC(0, 0);
    CP_WAIT0();
    __syncthreads();
    for (int c = 0; c < u.nch; c++) {
        if (c + 1 < u.nch) G_ASYNC(c + 1, (c + 1) & 1);
        const uint32_t bb = smb + (uint32_t)(c & 1) * BUFSTRIDE;
#pragma unroll
        for (int ks = 0; ks < 2; ks++) {
            const uint32_t ko = (uint32_t)(ks * 32);
            uint32_t bh[NF][2], bl[NF][2];
#pragma unroll
            for (int p = 0; p < NP; p++) {
                ldsm4(bh[2*p][0], bh[2*p][1], bh[2*p+1][0], bh[2*p+1][1],
                      bb + OFF_WH + b_off[p] + ko);
                ldsm4(bl[2*p][0], bl[2*p][1], bl[2*p+1][0], bl[2*p+1][1],
                      bb + OFF_WL + b_off[p] + ko);
            }
#pragma unroll
            for (int mf = 0; mf < 2; mf++) {
                uint32_t ah4[4], al4[4];
                ldsm4(ah4[0], ah4[1], ah4[2], ah4[3],
                      bb + OFF_AXH + a_off + (uint32_t)(mf * 1280) + ko);
                ldsm4(al4[0], al4[1], al4[2], al4[3],
                      bb + OFF_AXL + a_off + (uint32_t)(mf * 1280) + ko);
#pragma unroll
                for (int nf = 0; nf < NF; nf++) {
                    mma16816(acc[mf][nf], ah4, bh[nf]);
                    mma16816(acc[mf][nf], ah4, bl[nf]);
                    mma16816(acc[mf][nf], al4, bh[nf]);
                }
            }
        }
        if (c + 1 < u.nch) CP_WAIT0();
        __syncthreads();
    }
#undef G_ASYNC

#pragma unroll
    for (int mf = 0; mf < 2; mf++) {
#pragma unroll
        for (int half = 0; half < 2; half++) {
            int m = wm * 32 + mf * 16 + gq + half * 8;
            if (m >= u.mrows) continue;
            float* crow = u.C + (size_t)m * u.ldc;
            const float* car = u.cadd ? u.cadd + (size_t)m * u.ldadd : nullptr;
#pragma unroll
            for (int nf = 0; nf < NF; nf++) {
#pragma unroll
                for (int e = 0; e < 2; e++) {
                    int col = wn * (NF * 8) + nf * 8 + 2 * tq + e;
                    if (col < u.ncols) {
                        float v = acc[mf][nf][half * 2 + e];
                        if (u.bias) v += u.bias[col];
                        if (car) v += car[col];
                        crow[col] = v;
                    }
                }
            }
        }
    }
    __syncthreads();
}

// ---------------- fused layer-1/2 unit ----------------
struct FU {
    const __nv_bfloat16 *xh, *xl, *hh, *hl;
    const __nv_bfloat16 *wh, *wl;
    const float* bc;
    float* hfp;
    __nv_bfloat16 *oah, *oal;
    int m0, j0;
};

__device__ __noinline__ void fused_l12(const FU u, uint32_t smb)
{
    const int tid  = threadIdx.x;
    const int lane = tid & 31;
    const int w    = tid >> 5;
    const int wm   = w >> 2, wn = w & 3;
    const int gq   = lane >> 2, tq = lane & 3;

    float acc[2][6][4];
#pragma unroll
    for (int i = 0; i < 2; i++)
#pragma unroll
        for (int j = 0; j < 6; j++)
#pragma unroll
            for (int k = 0; k < 4; k++) acc[i][j][k] = 0.0f;

    const int ar = tid >> 2, aq = tid & 3;
    const int w2i = 512 + (tid & 255);
    const int w2r = w2i >> 2, w2q = w2i & 3;
    const bool w2hi = (tid < 256);
    const uint32_t soff  = (uint32_t)(ar * 80 + aq * 16);
    const uint32_t soff2 = (uint32_t)(w2r * 80 + w2q * 16);

    const uint32_t a_off = (uint32_t)((wm * 32 + (lane & 15)) * 80 + (lane >> 4) * 16);
    uint32_t b_off[3];
#pragma unroll
    for (int p = 0; p < 3; p++)
        b_off[p] = (uint32_t)((wn * 48 + p * 16 + ((lane >> 4) << 3) + (lane & 7)) * 80
                              + ((lane >> 3) & 1) * 16);

#define F_ASYNC(c, buf) do { \
    const uint32_t bb = smb + (uint32_t)(buf) * BUFSTRIDE; \
    size_t goA = (size_t)(u.m0 + ar) * H + (size_t)(c) * 32 + aq * 8; \
    size_t goW = (size_t)ar * H + (size_t)(c) * 32 + aq * 8; \
    size_t go2 = (size_t)w2r * H + (size_t)(c) * 32 + w2q * 8; \
    cpasync16(bb + OFF_AXH + soff, u.xh + goA); \
    cpasync16(bb + OFF_AXL + soff, u.xl + goA); \
    cpasync16(bb + OFF_AHH + soff, u.hh + goA); \
    cpasync16(bb + OFF_AHL + soff, u.hl + goA); \
    cpasync16(bb + OFF_WH + soff, u.wh + goW); \
    cpasync16(bb + OFF_WL + soff, u.wl + goW); \
    cpasync16(bb + (w2hi ? OFF_WH : OFF_WL) + soff2, (w2hi ? u.wh : u.wl) + go2); \
    CP_COMMIT(); \
} while (0)

    F_ASYNC(0, 0);
    CP_WAIT0();
    __syncthreads();
    for (int c = 0; c < 32; c++) {
        if (c + 1 < 32) F_ASYNC(c + 1, (c + 1) & 1);
        const uint32_t bb = smb + (uint32_t)(c & 1) * BUFSTRIDE;
#pragma unroll
        for (int ks = 0; ks < 2; ks++) {
            const uint32_t ko = (uint32_t)(ks * 32);
            uint32_t bh[6][2], bl[6][2];
#pragma unroll
            for (int p = 0; p < 3; p++) {
                ldsm4(bh[2*p][0], bh[2*p][1], bh[2*p+1][0], bh[2*p+1][1],
                      bb + OFF_WH + b_off[p] + ko);
                ldsm4(bl[2*p][0], bl[2*p][1], bl[2*p+1][0], bl[2*p+1][1],
                      bb + OFF_WL + b_off[p] + ko);
            }
#pragma unroll
            for (int mf = 0; mf < 2; mf++) {
                const uint32_t am = a_off + (uint32_t)(mf * 1280) + ko;
                uint32_t fh[4], fl[4];
                ldsm4(fh[0], fh[1], fh[2], fh[3], bb + OFF_AXH + am);
                ldsm4(fl[0], fl[1], fl[2], fl[3], bb + OFF_AXL + am);
#pragma unroll
                for (int nf = 0; nf < 3; nf++) {
                    mma16816(acc[mf][nf], fh, bh[nf]);
                    mma16816(acc[mf][nf], fh, bl[nf]);
                    mma16816(acc[mf][nf], fl, bh[nf]);
                }
                ldsm4(fh[0], fh[1], fh[2], fh[3], bb + OFF_AHH + am);
                ldsm4(fl[0], fl[1], fl[2], fl[3], bb + OFF_AHL + am);
#pragma unroll
                for (int nf = 3; nf < 6; nf++) {
                    mma16816(acc[mf][nf], fh, bh[nf]);
                    mma16816(acc[mf][nf], fh, bl[nf]);
                    mma16816(acc[mf][nf], fl, bh[nf]);
                }
            }
        }
        if (c + 1 < 32) CP_WAIT0();
        __syncthreads();
    }
#undef F_ASYNC

#pragma unroll
    for (int e = 0; e < 2; e++) {
        const int j = u.j0 + wn * 8 + 2 * tq + e;
        const float* bcb = u.bc + wn * 48 + 2 * tq + e;
        float b0 = bcb[0], b1 = bcb[8], b2 = bcb[16];
        float b3 = bcb[24], b4 = bcb[32], b5 = bcb[40];
#pragma unroll
        for (int mf = 0; mf < 2; mf++) {
#pragma unroll
            for (int half = 0; half < 2; half++) {
                int m = u.m0 + wm * 32 + mf * 16 + gq + half * 8;
                int ai = half * 2 + e;
                float ir = acc[mf][0][ai] + b0;
                float iz = acc[mf][1][ai] + b1;
                float in_ = acc[mf][2][ai] + b2;
                float hr = acc[mf][3][ai] + b3;
                float hz = acc[mf][4][ai] + b4;
                float hn = acc[mf][5][ai] + b5;
                float r = sigm(ir + hr), zz = sigm(iz + hz);
                float n = tanhf(in_ + r * hn);
                size_t idx = (size_t)m * H + j;
                float hv = (1.0f - zz) * n + zz * u.hfp[idx];
                u.hfp[idx] = hv;
                bsplit(hv, u.oah[idx], u.oal[idx]);
            }
        }
    }
    __syncthreads();
}

// ---------------- fused layer-0 unit ----------------
struct F0 {
    const __nv_bfloat16 *hh, *hl;
    const __nv_bfloat16 *wh, *wl;
    const float* bc;
    const int* inp;
    int t, m0, j0;
    float* hfp;
    __nv_bfloat16 *oah, *oal;
};

__device__ __noinline__ void fused_l0(const F0 u, uint32_t smb)
{
    const int tid  = threadIdx.x;
    const int lane = tid & 31;
    const int w    = tid >> 5;
    const int wm   = w >> 3, wn = w & 7;
    const int gq   = lane >> 2, tq = lane & 3;

    float acc[2][3][4];
#pragma unroll
    for (int i = 0; i < 2; i++)
#pragma unroll
        for (int j = 0; j < 3; j++)
#pragma unroll
            for (int k = 0; k < 4; k++) acc[i][j][k] = 0.0f;

    const int ar = tid >> 2, aq = tid & 3;
    const bool aload = (tid < 256);
    const int w2i = 512 + (tid & 255);
    const int w2r = w2i >> 2, w2q = w2i & 3;
    const bool w2hi = (tid < 256);
    const uint32_t soff  = (uint32_t)(ar * 80 + aq * 16);
    const uint32_t soff2 = (uint32_t)(w2r * 80 + w2q * 16);

    const uint32_t a_off = (uint32_t)((wm * 32 + (lane & 15)) * 80 + (lane >> 4) * 16);
    const uint32_t b_off0 = (uint32_t)((wn * 24 + ((lane >> 4) << 3) + (lane & 7)) * 80
                                       + ((lane >> 3) & 1) * 16);
    const uint32_t b_off2 = (uint32_t)((wn * 24 + 16 + (lane & 7)) * 80
                                       + ((lane >> 3) & 1) * 16);

#define Z_ASYNC(c, buf) do { \
    const uint32_t bb = smb + (uint32_t)(buf) * BUFSTRIDE; \
    size_t goW = (size_t)ar * H + (size_t)(c) * 32 + aq * 8; \
    size_t go2 = (size_t)w2r * H + (size_t)(c) * 32 + w2q * 8; \
    if (aload) { size_t goA = (size_t)(u.m0 + ar) * H + (size_t)(c) * 32 + aq * 8; \
        cpasync16(bb + OFF_AXH + soff, u.hh + goA); \
        cpasync16(bb + OFF_AXL + soff, u.hl + goA); } \
    cpasync16(bb + OFF_WH + soff, u.wh + goW); \
    cpasync16(bb + OFF_WL + soff, u.wl + goW); \
    cpasync16(bb + (w2hi ? OFF_WH : OFF_WL) + soff2, (w2hi ? u.wh : u.wl) + go2); \
    CP_COMMIT(); \
} while (0)

    Z_ASYNC(0, 0);
    CP_WAIT0();
    __syncthreads();
    for (int c = 0; c < 32; c++) {
        if (c + 1 < 32) Z_ASYNC(c + 1, (c + 1) & 1);
        const uint32_t bb = smb + (uint32_t)(c & 1) * BUFSTRIDE;
#pragma unroll
        for (int ks = 0; ks < 2; ks++) {
            const uint32_t ko = (uint32_t)(ks * 32);
            uint32_t bh[3][2], bl[3][2];
            ldsm4(bh[0][0], bh[0][1], bh[1][0], bh[1][1], bb + OFF_WH + b_off0 + ko);
            ldsm4(bl[0][0], bl[0][1], bl[1][0], bl[1][1], bb + OFF_WL + b_off0 + ko);
            ldsm2(bh[2][0], bh[2][1], bb + OFF_WH + b_off2 + ko);
            ldsm2(bl[2][0], bl[2][1], bb + OFF_WL + b_off2 + ko);
#pragma unroll
            for (int mf = 0; mf < 2; mf++) {
                const uint32_t am = a_off + (uint32_t)(mf * 1280) + ko;
                uint32_t fh[4], fl[4];
                ldsm4(fh[0], fh[1], fh[2], fh[3], bb + OFF_AXH + am);
                ldsm4(fl[0], fl[1], fl[2], fl[3], bb + OFF_AXL + am);
#pragma unroll
                for (int nf = 0; nf < 3; nf++) {
                    mma16816(acc[mf][nf], fh, bh[nf]);
                    mma16816(acc[mf][nf], fh, bl[nf]);
                    mma16816(acc[mf][nf], fl, bh[nf]);
                }
            }
        }
        if (c + 1 < 32) CP_WAIT0();
        __syncthreads();
    }
#undef Z_ASYNC

#pragma unroll
    for (int e = 0; e < 2; e++) {
        const int j = u.j0 + wn * 8 + 2 * tq + e;
        const float* bcb = u.bc + wn * 24 + 2 * tq + e;
        float b0 = bcb[0], b1 = bcb[8], b2 = bcb[16];
#pragma unroll
        for (int mf = 0; mf < 2; mf++) {
#pragma unroll
            for (int half = 0; half < 2; half++) {
                int m = u.m0 + wm * 32 + mf * 16 + gq + half * 8;
                int ai = half * 2 + e;
                int tok = (u.t == 0) ? START_TOK : u.inp[m * S + u.t - 1];
                const float* tr = g_tokt + (size_t)tok * H3 + j;
                const float* gc = g_gi0c + (size_t)m * H3 + j;
                float ir = tr[0] + gc[0];
                float iz = tr[H] + gc[H];
                float in_ = tr[2 * H] + gc[2 * H];
                float hr = acc[mf][0][ai] + b0;
                float hz = acc[mf][1][ai] + b1;
                float hn = acc[mf][2][ai] + b2;
                float r = sigm(ir + hr), zz = sigm(iz + hz);
                float n = tanhf(in_ + r * hn);
                size_t idx = (size_t)m * H + j;
                float hv = (1.0f - zz) * n + zz * u.hfp[idx];
                u.hfp[idx] = hv;
                bsplit(hv, u.oah[idx], u.oal[idx]);
            }
        }
    }
    __syncthreads();
}

// ---------------- persistent kernel ----------------
__global__ __launch_bounds__(NTH, 1) void decoder_k(
    const int* __restrict__ inputs, const float* __restrict__ z,
    const float* __restrict__ cond, const float* __restrict__ emb,
    const float* __restrict__ i2h_w, const float* __restrict__ i2h_b,
    const float* __restrict__ out_w, const float* __restrict__ out_b,
    const float* __restrict__ wih0, const float* __restrict__ whh0,
    const float* __restrict__ bih0, const float* __restrict__ bhh0,
    const float* __restrict__ wih1, const float* __restrict__ whh1,
    const float* __restrict__ bih1, const float* __restrict__ bhh1,
    const float* __restrict__ wih2, const float* __restrict__ whh2,
    const float* __restrict__ bih2, const float* __restrict__ bhh2,
    float* __restrict__ out)
{
    extern __shared__ __align__(16) char smem[];
    uint32_t smb;
    asm("{ .reg .u64 t; cvta.to.shared.u64 t, %1; cvt.u32.u64 %0, t; }"
        : "=r"(smb) : "l"(smem));

    const int tid = threadIdx.x;
    const unsigned nb = gridDim.x;
    const int gid = blockIdx.x * NTH + tid;
    const int gstride = nb * NTH;

    // ---- P0: splits + gate-interleaved weight layouts ----
    for (int i = gid; i < 3072 * 1024; i += gstride) {
        int rd = i >> 10, k = i & 1023;
        int jb = rd / 192, r2 = rd - jb * 192;
        int jo = r2 / 24, r3 = r2 - jo * 24;
        int g = r3 >> 3, jr = r3 & 7;
        int j = jb * 64 + jo * 8 + jr;
        bsplit(whh0[(size_t)(g * H + j) * H + k], g_wc0h[i], g_wc0l[i]);
    }
    {
        const float* wi[2] = {wih1, wih2};
        const float* wr[2] = {whh1, whh2};
        __nv_bfloat16* dh[2] = {g_wc1h, g_wc2h};
        __nv_bfloat16* dl[2] = {g_wc1l, g_wc2l};
        for (int l = 0; l < 2; l++)
            for (int i = gid; i < 6144 * 1024; i += gstride) {
                int rd = i >> 10, k = i & 1023;
                int jb = rd / 192, r2 = rd - jb * 192;
                int jo = r2 / 48, r3 = r2 - jo * 48;
                int g = r3 >> 3, jr = r3 & 7;
                int j = jb * 32 + jo * 8 + jr;
                float v = (g < 3) ? wi[l][(size_t)(g * H + j) * H + k]
                                  : wr[l][(size_t)((g - 3) * H + j) * H + k];
                bsplit(v, dh[l][i], dl[l][i]);
            }
    }
    for (int i = gid; i < 3072; i += gstride) {
        int jb = i / 192, r2 = i - jb * 192;
        int jo = r2 / 24, r3 = r2 - jo * 24;
        int g = r3 >> 3, jr = r3 & 7;
        g_bc0[i] = bhh0[g * H + jb * 64 + jo * 8 + jr];
    }
    {
        const float* bi[2] = {bih1, bih2};
        const float* br[2] = {bhh1, bhh2};
        float* bd[2] = {g_bc1, g_bc2};
        for (int l = 0; l < 2; l++)
            for (int i = gid; i < 6144; i += gstride) {
                int jb = i / 192, r2 = i - jb * 192;
                int jo = r2 / 48, r3 = r2 - jo * 48;
                int g = r3 >> 3, jr = r3 & 7;
                int j = jb * 32 + jo * 8 + jr;
                bd[l][i] = (g < 3) ? bi[l][g * H + j] : br[l][(g - 3) * H + j];
            }
    }
    for (int i = gid; i < H * INSZ; i += gstride) bsplit(i2h_w[i], g_i2hh[i], g_i2hl[i]);
    for (int i = gid; i < H3 * EMB; i += gstride) {
        int r = i >> 9, c = i & 511;
        bsplit(wih0[(size_t)r * (EMB + INSZ) + c], g_w0ah[i], g_w0al[i]);
    }
    for (int i = gid; i < H3 * H; i += gstride) {
        int r = i >> 10, c = i & 1023;
        bsplit(wih0[(size_t)r * (EMB + INSZ) + EMB + c], g_w0bh[i], g_w0bl[i]);
    }
    for (int i = gid; i < 128 * EMB; i += gstride) {
        int r = i >> 9, c = i & 511;
        bsplit(r < V ? emb[r * EMB + c] : 0.0f, g_embh[i], g_embl[i]);
    }
    for (int i = gid; i < 128 * H; i += gstride) {
        int r = i >> 10, c = i & 1023;
        bsplit(r < V ? out_w[(size_t)r * (H + INSZ) + c] : 0.0f, g_owh[i], g_owl[i]);
        bsplit(r < V ? out_w[(size_t)r * (H + INSZ) + H + c] : 0.0f, g_ow2h[i], g_ow2l[i]);
    }
    for (int i = gid; i < B * INSZ; i += gstride) {
        int b = i >> 10, jx = i & 1023;
        float v = (jx < 512) ? z[b * 512 + jx] : cond[b * 512 + jx - 512];
        bsplit(v, g_dech[i], g_decl[i]);
    }
    grid_bar();

    // ---- P2: prologue GEMMs (116 units) ----
    for (int u = blockIdx.x; u < 116; u += nb) {
        if (u < 32) {
            int mt = u & 3, nt = u >> 2;
            mma_unit<4>(mk_mu(
                g_dech + (size_t)(mt * 128) * INSZ, g_decl + (size_t)(mt * 128) * INSZ, INSZ,
                g_i2hh + (size_t)(nt * 128) * INSZ, g_i2hl + (size_t)(nt * 128) * INSZ, INSZ,
                i2h_b + nt * 128, nullptr, 0,
                g_h0 + (size_t)(mt * 128) * H + nt * 128, H, 32, 128, 128), smb);
        } else if (u < 96) {
            int q = u - 32, mt = q & 3, nt = q >> 2;
            mma_unit<6>(mk_mu(
                g_dech + (size_t)(mt * 128) * INSZ, g_decl + (size_t)(mt * 128) * INSZ, INSZ,
                g_w0bh + (size_t)(nt * 192) * H, g_w0bl + (size_t)(nt * 192) * H, H,
                bih0 + nt * 192, nullptr, 0,
                g_gi0c + (size_t)(mt * 128) * H3 + nt * 192, H3, 32, 128, 192), smb);
        } else if (u < 112) {
            int nt = u - 96;
            mma_unit<6>(mk_mu(
                g_embh, g_embl, EMB,
                g_w0ah + (size_t)(nt * 192) * EMB, g_w0al + (size_t)(nt * 192) * EMB, EMB,
                nullptr, nullptr, 0,
                g_tokt + nt * 192, H3, 16, V, 192), smb);
        } else {
            int mt = u - 112;
            mma_unit<4>(mk_mu(
                g_dech + (size_t)(mt * 128) * INSZ, g_decl + (size_t)(mt * 128) * INSZ, INSZ,
                g_ow2h, g_ow2l, H,
                out_b, nullptr, 0,
                g_logc + (size_t)(mt * 128) * V, V, 32, 128, V), smb);
        }
    }
    grid_bar();

    // ---- P3: broadcast h_init + splits into buffer 0 ----
    for (int i = gid; i < B * H; i += gstride) {
        float v = g_h0[i];
        g_h1[i] = v; g_h2[i] = v;
        __nv_bfloat16 hi, lo;
        bsplit(v, hi, lo);
        g_a0h[0][i] = hi; g_a0l[0][i] = lo;
        g_a1h[0][i] = hi; g_a1l[0][i] = lo;
        g_a2h[0][i] = hi; g_a2l[0][i] = lo;
    }
    grid_bar();

    // ---- recurrent loop: 3 barriers/step ----
    for (int t = 0; t < S; t++) {
        const int cur = t & 1, nxt = cur ^ 1;

        {
            const int U = 128 + (t > 0 ? 4 : 0);
            for (int u = blockIdx.x; u < U; u += nb) {
                if (u < 128) {
                    int mb = u & 7, jb = u >> 3;
                    F0 f;
                    f.hh = g_a0h[cur]; f.hl = g_a0l[cur];
                    f.wh = g_wc0h + (size_t)(jb * 192) * H;
                    f.wl = g_wc0l + (size_t)(jb * 192) * H;
                    f.bc = g_bc0 + jb * 192;
                    f.inp = inputs; f.t = t;
                    f.m0 = mb * 64; f.j0 = jb * 64;
                    f.hfp = g_h0; f.oah = g_a0h[nxt]; f.oal = g_a0l[nxt];
                    fused_l0(f, smb);
                } else {
                    int mt = u - 128;
                    mma_unit<4>(mk_mu(
                        g_a2h[cur] + (size_t)(mt * 128) * H,
                        g_a2l[cur] + (size_t)(mt * 128) * H, H,
                        g_owh, g_owl, H,
                        nullptr, g_logc + (size_t)(mt * 128) * V, V,
                        out + (size_t)(mt * 128) * (S * V) + (size_t)(t - 1) * V,
                        S * V, 32, 128, V), smb);
                }
            }
        }
        grid_bar();

        for (int u = blockIdx.x; u < 128; u += nb) {
            int mb = u & 3, jb = u >> 2;
            FU f;
            f.xh = g_a0h[nxt]; f.xl = g_a0l[nxt];
            f.hh = g_a1h[cur]; f.hl = g_a1l[cur];
            f.wh = g_wc1h + (size_t)(jb * 192) * H;
            f.wl = g_wc1l + (size_t)(jb * 192) * H;
            f.bc = g_bc1 + jb * 192;
            f.m0 = mb * 128; f.j0 = jb * 32;
            f.hfp = g_h1; f.oah = g_a1h[nxt]; f.oal = g_a1l[nxt];
            fused_l12(f, smb);
        }
        grid_bar();

        for (int u = blockIdx.x; u < 128; u += nb) {
            int mb = u & 3, jb = u >> 2;
            FU f;
            f.xh = g_a1h[nxt]; f.xl = g_a1l[nxt];
            f.hh = g_a2h[cur]; f.hl = g_a2l[cur];
            f.wh = g_wc2h + (size_t)(jb * 192) * H;
            f.wl = g_wc2l + (size_t)(jb * 192) * H;
            f.bc = g_bc2 + jb * 192;
            f.m0 = mb * 128; f.j0 = jb * 32;
            f.hfp = g_h2; f.oah = g_a2h[nxt]; f.oal = g_a2l[nxt];
            fused_l12(f, smb);
        }
        grid_bar();
    }

    // ---- final logits ----
    for (int u = blockIdx.x; u < 4; u += nb) {
        int mt = u;
        mma_unit<4>(mk_mu(
            g_a2h[S & 1] + (size_t)(mt * 128) * H,
            g_a2l[S & 1] + (size_t)(mt * 128) * H, H,
            g_owh, g_owl, H,
            nullptr, g_logc + (size_t)(mt * 128) * V, V,
            out + (size_t)(mt * 128) * (S * V) + (size_t)(S - 1) * V,
            S * V, 32, 128, V), smb);
    }
}

// ---------------- host ----------------
extern "C" void kernel_launch(void* const* d_in, const int* in_sizes, int n_in,
                              void* d_out, int out_size)
{
    (void)in_sizes; (void)n_in; (void)out_size;

    const int*   inputs = (const int*)  d_in[0];
    const float* z      = (const float*)d_in[1];
    const float* cond   = (const float*)d_in[2];
    const float* emb    = (const float*)d_in[4];
    const float* i2h_w  = (const float*)d_in[5];
    const float* i2h_b  = (const float*)d_in[6];
    const float* out_w  = (const float*)d_in[7];
    const float* out_b  = (const float*)d_in[8];
    const float* wih0 = (const float*)d_in[9];
    const float* whh0 = (const float*)d_in[10];
    const float* bih0 = (const float*)d_in[11];
    const float* bhh0 = (const float*)d_in[12];
    const float* wih1 = (const float*)d_in[13];
    const float* whh1 = (const float*)d_in[14];
    const float* bih1 = (const float*)d_in[15];
    const float* bhh1 = (const float*)d_in[16];
    const float* wih2 = (const float*)d_in[17];
    const float* whh2 = (const float*)d_in[18];
    const float* bih2 = (const float*)d_in[19];
    const float* bhh2 = (const float*)d_in[20];
    float* out = (float*)d_out;

    cudaFuncSetAttribute(decoder_k, cudaFuncAttributeMaxDynamicSharedMemorySize,
                         SMEM_TOTAL);

    int dev = 0;
    cudaGetDevice(&dev);
    int sms = 148;
    cudaDeviceGetAttribute(&sms, cudaDevAttrMultiProcessorCount, dev);
    int bpm = 1;
    cudaOccupancyMaxActiveBlocksPerMultiprocessor(&bpm, decoder_k, NTH, SMEM_TOTAL);
    if (bpm < 1) bpm = 1;

    decoder_k<<<sms * bpm, NTH, SMEM_TOTAL>>>(
        inputs, z, cond, emb, i2h_w, i2h_b, out_w, out_b,
        wih0, whh0, bih0, bhh0, wih1, whh1, bih1, bhh1,
        wih2, whh2, bih2, bhh2, out);
}